// round 11
// baseline (speedup 1.0000x reference)
#include <cuda_runtime.h>
#include <math.h>

#define Bsz 16
#define Tn 16
#define FDIM 64
#define ODIM 8
#define NQ 10
#define NA 4
#define NROTS 80
#define QROTS 40
#define NS 1024
#define NANC 16
#define STATE_PER_B (NS*NANC)
#define TOTAL_AMPS (Bsz*STATE_PER_B)

typedef unsigned long long u64;

__device__ float4 g_state4[TOTAL_AMPS/2];
#define G_STATE  ((float2*)g_state4)
#define G_STATEU ((u64*)g_state4)
__device__ float2 g_csn[Bsz*Tn*NROTS];
__device__ float2 g_qff[QROTS];
__device__ float2 g_M[3][256];
__device__ float2 g_v0[16];

// ------------------------------------------------------- packed f32x2 ops ---
__device__ __forceinline__ u64 pk2(float x, float y) {
    u64 r; asm("mov.b64 %0, {%1, %2};" : "=l"(r) : "f"(x), "f"(y)); return r;
}
__device__ __forceinline__ float2 upk(u64 a) {
    float2 f; asm("mov.b64 {%0, %1}, %2;" : "=f"(f.x), "=f"(f.y) : "l"(a)); return f;
}
__device__ __forceinline__ u64 mul2(u64 a, u64 b) {
    u64 d; asm("mul.rn.f32x2 %0, %1, %2;" : "=l"(d) : "l"(a), "l"(b)); return d;
}
__device__ __forceinline__ u64 fma2(u64 a, u64 b, u64 c) {
    u64 d; asm("fma.rn.f32x2 %0, %1, %2, %3;" : "=l"(d) : "l"(a), "l"(b), "l"(c)); return d;
}
__device__ __forceinline__ u64 swap2(u64 a) {
    float2 f = upk(a); return pk2(f.y, f.x);
}

// -------------------------------------------------- pre (angles + setup) ----
__global__ void __launch_bounds__(256) k_pre(const float* __restrict__ x,
                                             const float* __restrict__ Wfp,
                                             const float* __restrict__ bfp,
                                             const float* __restrict__ prep_p,
                                             const float* __restrict__ sig_ang,
                                             const float* __restrict__ qff_p)
{
    int tid = threadIdx.x;
    if (blockIdx.x < 256) {
        int bt = blockIdx.x;
        int b = bt >> 4, t = bt & 15;
        __shared__ float h[64];
        if (tid < 64) {
            int f = tid;
            int k = f >> 1;
            float div = expf((float)(2*k) * (-logf(10000.0f) / 64.0f));
            float arg = (float)t * div;
            float pe = (f & 1) ? cosf(arg) : sinf(arg);
            h[f] = x[(b*64 + f)*16 + t] + pe;
        }
        __syncthreads();
        if (tid < NROTS) {
            float acc = bfp[tid];
            const float* w = Wfp + tid*64;
            #pragma unroll
            for (int f = 0; f < 64; ++f) acc += h[f]*w[f];
            float sg = 1.0f / (1.0f + expf(-acc));
            float sn, cs;
            sincosf(3.14159265358979323846f * sg, &sn, &cs);
            g_csn[bt*NROTS + tid] = make_float2(cs, sn);
        }
        return;
    }
    __shared__ float2 sU[16][16];
    int t = tid;
    if (t < 16) {
        float2 v[16];
        #pragma unroll
        for (int i = 0; i < 16; ++i) v[i] = make_float2(0.f, 0.f);
        v[t] = make_float2(1.f, 0.f);
        for (int ly = 0; ly < 4; ++ly) {
            for (int qi = 0; qi < 4; ++qi) {
                int p = 3 - qi;
                float thy = prep_p[(ly*4 + qi)*2 + 0];
                float thz = prep_p[(ly*4 + qi)*2 + 1];
                float c, s;
                sincosf(0.5f*thy, &s, &c);
                for (int m = 0; m < 8; ++m) {
                    int i0 = ((m >> p) << (p+1)) | (m & ((1 << p) - 1));
                    int i1 = i0 | (1 << p);
                    float2 a0 = v[i0], a1 = v[i1];
                    v[i0] = make_float2(c*a0.x - s*a1.x, c*a0.y - s*a1.y);
                    v[i1] = make_float2(s*a0.x + c*a1.x, s*a0.y + c*a1.y);
                }
                float cz, sz;
                sincosf(0.5f*thz, &sz, &cz);
                for (int i = 0; i < 16; ++i) {
                    float im = ((i >> p) & 1) ? sz : -sz;
                    float2 a = v[i];
                    v[i] = make_float2(cz*a.x - im*a.y, cz*a.y + im*a.x);
                }
            }
            for (int i = 0; i < 3; ++i) {
                int pc = 3 - i, pt = 2 - i;
                for (int idx = 0; idx < 16; ++idx) {
                    if (((idx >> pc) & 1) == 1 && ((idx >> pt) & 1) == 0) {
                        int j = idx | (1 << pt);
                        float2 tmp = v[idx]; v[idx] = v[j]; v[j] = tmp;
                    }
                }
            }
        }
        #pragma unroll
        for (int r = 0; r < 16; ++r) sU[r][t] = v[r];
    }
    __syncthreads();
    if (t < 16) {
        float c0, s0;
        sincosf(sig_ang[0], &s0, &c0);
        float2 u = sU[t][0];
        g_v0[t] = make_float2(c0*u.x - s0*u.y, c0*u.y + s0*u.x);
    }
    if (t >= 192 && t < 192 + QROTS) {
        float c, s;
        sincosf(0.5f * qff_p[t - 192], &s, &c);
        g_qff[t - 192] = make_float2(c, s);
    }
    {
        int j = t >> 4, k = t & 15;
        for (int m = 0; m < 2; ++m) {
            float cp, sp;
            sincosf(sig_ang[m+1], &sp, &cp);
            float2 acc = make_float2(0.f, 0.f);
            #pragma unroll
            for (int a = 0; a < 16; ++a) {
                float2 uja = sU[j][a];
                float2 uka = sU[k][a];
                float dr = cp, di = (a == 0) ? sp : -sp;
                float2 dc = make_float2(dr*uka.x + di*uka.y, di*uka.x - dr*uka.y);
                acc.x += uja.x*dc.x - uja.y*dc.y;
                acc.y += uja.x*dc.y + uja.y*dc.x;
            }
            g_M[m][j*16 + k] = acc;
        }
        float cp, sp;
        sincosf(sig_ang[3], &sp, &cp);
        float dr = cp, di = (j == 0) ? sp : -sp;
        float2 u2 = sU[k][j];
        g_M[2][j*16 + k] = make_float2(dr*u2.x + di*u2.y, di*u2.x - dr*u2.y);
    }
}

// ------------------------------------------------------- gate primitives ----
// layout per block: amplitude s: lane=s[4:0], reg=s[7:5] (8 u64/lane), warp=s[9:8].
// One CTA (128 thr) carries TWO blocks: v0 (c even), v1 (c odd).

template<int PB>
__device__ __forceinline__ void ry_reg(u64* v, float cc, float ss)
{
    u64 cc2 = pk2(cc, cc), ss2 = pk2(ss, ss), nss2 = pk2(-ss, -ss);
    #pragma unroll
    for (int m = 0; m < 4; ++m) {
        int i0 = ((m >> PB) << (PB+1)) | (m & ((1 << PB) - 1));
        int i1 = i0 | (1 << PB);
        u64 a0 = v[i0], a1 = v[i1];
        v[i0] = fma2(cc2, a0, mul2(nss2, a1));
        v[i1] = fma2(cc2, a1, mul2(ss2, a0));
    }
}

__device__ __forceinline__ void ry_lane(u64* v, int pl, float cc, float ss, int lane)
{
    float sg = ((lane >> pl) & 1) ? ss : -ss;
    u64 cc2 = pk2(cc, cc), sg2 = pk2(sg, sg);
    int mk = 1 << pl;
    #pragma unroll
    for (int q = 0; q < 8; ++q) {
        float2 f = upk(v[q]);
        float px = __shfl_xor_sync(0xffffffffu, f.x, mk);
        float py = __shfl_xor_sync(0xffffffffu, f.y, mk);
        v[q] = fma2(cc2, v[q], mul2(sg2, pk2(px, py)));
    }
}

template<int PCB, int PTB>
__device__ __forceinline__ void crx_rr(u64* v, float cc, float ss)
{
    u64 cc2 = pk2(cc, cc), ssv2 = pk2(ss, -ss);
    #pragma unroll
    for (int i = 0; i < 8; ++i) {
        if ((((i >> PCB) & 1) == 1) && (((i >> PTB) & 1) == 0)) {
            int i1 = i | (1 << PTB);
            u64 a0 = v[i], a1 = v[i1];
            v[i]  = fma2(cc2, a0, mul2(ssv2, swap2(a1)));
            v[i1] = fma2(cc2, a1, mul2(ssv2, swap2(a0)));
        }
    }
}

__device__ __forceinline__ void crx_shfl(u64* v, int pt, bool act, float cc, float ss)
{
    float ccl = act ? cc : 1.f, ssl = act ? ss : 0.f;
    u64 cc2 = pk2(ccl, ccl), ssv2 = pk2(ssl, -ssl);
    int mk = 1 << pt;
    #pragma unroll
    for (int q = 0; q < 8; ++q) {
        float2 f = upk(v[q]);
        float px = __shfl_xor_sync(0xffffffffu, f.x, mk);
        float py = __shfl_xor_sync(0xffffffffu, f.y, mk);
        v[q] = fma2(cc2, v[q], mul2(ssv2, pk2(py, px)));
    }
}

template<int PCB>
__device__ __forceinline__ void crx_rl(u64* v, int pt, float cc, float ss)
{
    u64 cc2 = pk2(cc, cc), ssv2 = pk2(ss, -ss);
    int mk = 1 << pt;
    #pragma unroll
    for (int q = 0; q < 8; ++q) {
        if ((q >> PCB) & 1) {
            float2 f = upk(v[q]);
            float px = __shfl_xor_sync(0xffffffffu, f.x, mk);
            float py = __shfl_xor_sync(0xffffffffu, f.y, mk);
            v[q] = fma2(cc2, v[q], mul2(ssv2, pk2(py, px)));
        }
    }
}

template<int PTB>
__device__ __forceinline__ void crx_reg_tgt(u64* v, bool act, float cc, float ss)
{
    float ccl = act ? cc : 1.f, ssl = act ? ss : 0.f;
    u64 cc2 = pk2(ccl, ccl), ssv2 = pk2(ssl, -ssl);
    #pragma unroll
    for (int m = 0; m < 4; ++m) {
        int i0 = ((m >> PTB) << (PTB+1)) | (m & ((1 << PTB) - 1));
        int i1 = i0 | (1 << PTB);
        u64 a0 = v[i0], a1 = v[i1];
        v[i0] = fma2(cc2, a0, mul2(ssv2, swap2(a1)));
        v[i1] = fma2(cc2, a1, mul2(ssv2, swap2(a0)));
    }
}

// ----- dual cross-warp exchanges (one barrier serves both blocks) -----------
struct Xch {
    u64* base; int tog; int tid;
    __device__ __forceinline__ u64* next() { u64* p = base + ((tog & 1) << 11); ++tog; return p; }
};

__device__ __forceinline__ void ry_warp_d(u64* v0, u64* v1, Xch& X, int wb,
                                          float cc0, float ss0, float cc1, float ss1)
{
    u64* b = X.next();
    int tid = X.tid, xv = 32 << wb;
    #pragma unroll
    for (int i = 0; i < 8; ++i) { b[i*128 + tid] = v0[i]; b[1024 + i*128 + tid] = v1[i]; }
    __syncthreads();
    int hb = (tid >> (5 + wb)) & 1;
    float sg0 = hb ? ss0 : -ss0;
    float sg1 = hb ? ss1 : -ss1;
    u64 c0 = pk2(cc0, cc0), g0 = pk2(sg0, sg0);
    u64 c1 = pk2(cc1, cc1), g1 = pk2(sg1, sg1);
    #pragma unroll
    for (int i = 0; i < 8; ++i) {
        v0[i] = fma2(c0, v0[i], mul2(g0, b[i*128 + (tid ^ xv)]));
        v1[i] = fma2(c1, v1[i], mul2(g1, b[1024 + i*128 + (tid ^ xv)]));
    }
}

__device__ __forceinline__ void crx_warp_tgt_d(u64* v0, u64* v1, Xch& X, int twb, bool act,
                                               float cc0, float ss0, float cc1, float ss1)
{
    u64* b = X.next();
    int tid = X.tid, xv = 32 << twb;
    #pragma unroll
    for (int i = 0; i < 8; ++i) { b[i*128 + tid] = v0[i]; b[1024 + i*128 + tid] = v1[i]; }
    __syncthreads();
    float cl0 = act ? cc0 : 1.f, sl0 = act ? ss0 : 0.f;
    float cl1 = act ? cc1 : 1.f, sl1 = act ? ss1 : 0.f;
    u64 c0 = pk2(cl0, cl0), s0 = pk2(sl0, -sl0);
    u64 c1 = pk2(cl1, cl1), s1 = pk2(sl1, -sl1);
    #pragma unroll
    for (int i = 0; i < 8; ++i) {
        v0[i] = fma2(c0, v0[i], mul2(s0, swap2(b[i*128 + (tid ^ xv)])));
        v1[i] = fma2(c1, v1[i], mul2(s1, swap2(b[1024 + i*128 + (tid ^ xv)])));
    }
}

// CRX control on reg bit 2 (regs 4..7), target warp bit twb
__device__ __forceinline__ void crx_rw_d(u64* v0, u64* v1, Xch& X, int twb,
                                         float cc0, float ss0, float cc1, float ss1)
{
    u64* b = X.next();
    int tid = X.tid, xv = 32 << twb;
    #pragma unroll
    for (int i = 0; i < 4; ++i) { b[i*128 + tid] = v0[4 + i]; b[1024 + i*128 + tid] = v1[4 + i]; }
    __syncthreads();
    u64 c0 = pk2(cc0, cc0), s0 = pk2(ss0, -ss0);
    u64 c1 = pk2(cc1, cc1), s1 = pk2(ss1, -ss1);
    #pragma unroll
    for (int i = 0; i < 4; ++i) {
        v0[4 + i] = fma2(c0, v0[4 + i], mul2(s0, swap2(b[i*128 + (tid ^ xv)])));
        v1[4 + i] = fma2(c1, v1[4 + i], mul2(s1, swap2(b[1024 + i*128 + (tid ^ xv)])));
    }
}

// -------------------------------------------------------- layer pieces ------
// qubit q acts on s bit 9-q. bits: lane 0-4, reg 5-7 (PB 0-2), warp 8-9 (wb 0-1)
#define CC0(K) (a0[K].x)
#define SS0(K) (sgn*a0[K].y)
#define CC1(K) (a1[K].x)
#define SS1(K) (sgn*a1[K].y)

__device__ __forceinline__ void ry_all_d(u64* v0, u64* v1, Xch& X,
                                         const float2* __restrict__ a0,
                                         const float2* __restrict__ a1,
                                         float sgn, int lane)
{
    ry_warp_d(v0, v1, X, 1, CC0(0), SS0(0), CC1(0), SS1(0));   // q0 -> bit9
    ry_warp_d(v0, v1, X, 0, CC0(1), SS0(1), CC1(1), SS1(1));   // q1 -> bit8
    ry_reg<2>(v0, CC0(2), SS0(2)); ry_reg<2>(v1, CC1(2), SS1(2));
    ry_reg<1>(v0, CC0(3), SS0(3)); ry_reg<1>(v1, CC1(3), SS1(3));
    ry_reg<0>(v0, CC0(4), SS0(4)); ry_reg<0>(v1, CC1(4), SS1(4));
    #pragma unroll 1
    for (int pl = 4; pl >= 0; --pl) {            // q5..q9 -> lane bits 4..0
        ry_lane(v0, pl, CC0(9-pl), SS0(9-pl), lane);
        ry_lane(v1, pl, CC1(9-pl), SS1(9-pl), lane);
    }
}

// ring A: gate k = (ctrl bit k, tgt bit k-1 mod 10), angle [k]
__device__ __forceinline__ void ring_a_d(u64* v0, u64* v1, Xch& X,
                                         const float2* __restrict__ a0,
                                         const float2* __restrict__ a1,
                                         float sgn, int lane, int tid, bool rev)
{
    if (!rev) {
        crx_warp_tgt_d(v0, v1, X, 1, lane & 1, CC0(0), SS0(0), CC1(0), SS1(0));      // c b0, t b9
        #pragma unroll 1
        for (int j = 1; j <= 4; ++j) {
            bool act = (lane >> j) & 1;
            crx_shfl(v0, j-1, act, CC0(j), SS0(j));
            crx_shfl(v1, j-1, act, CC1(j), SS1(j));
        }
        crx_rl<0>(v0, 4, CC0(5), SS0(5)); crx_rl<0>(v1, 4, CC1(5), SS1(5));           // c b5, t b4
        crx_rr<1,0>(v0, CC0(6), SS0(6)); crx_rr<1,0>(v1, CC1(6), SS1(6));             // c b6, t b5
        crx_rr<2,1>(v0, CC0(7), SS0(7)); crx_rr<2,1>(v1, CC1(7), SS1(7));             // c b7, t b6
        { bool act = (tid >> 5) & 1;
          crx_reg_tgt<2>(v0, act, CC0(8), SS0(8)); crx_reg_tgt<2>(v1, act, CC1(8), SS1(8)); }
        crx_warp_tgt_d(v0, v1, X, 0, (tid >> 6) & 1, CC0(9), SS0(9), CC1(9), SS1(9)); // c b9, t b8
    } else {
        crx_warp_tgt_d(v0, v1, X, 0, (tid >> 6) & 1, CC0(9), SS0(9), CC1(9), SS1(9));
        { bool act = (tid >> 5) & 1;
          crx_reg_tgt<2>(v0, act, CC0(8), SS0(8)); crx_reg_tgt<2>(v1, act, CC1(8), SS1(8)); }
        crx_rr<2,1>(v0, CC0(7), SS0(7)); crx_rr<2,1>(v1, CC1(7), SS1(7));
        crx_rr<1,0>(v0, CC0(6), SS0(6)); crx_rr<1,0>(v1, CC1(6), SS1(6));
        crx_rl<0>(v0, 4, CC0(5), SS0(5)); crx_rl<0>(v1, 4, CC1(5), SS1(5));
        #pragma unroll 1
        for (int j = 4; j >= 1; --j) {
            bool act = (lane >> j) & 1;
            crx_shfl(v0, j-1, act, CC0(j), SS0(j));
            crx_shfl(v1, j-1, act, CC1(j), SS1(j));
        }
        crx_warp_tgt_d(v0, v1, X, 1, lane & 1, CC0(0), SS0(0), CC1(0), SS1(0));
    }
}

// ring B: k0(c0,t1) k1(c9,t0) k2(c8,t9) k3(c7,t8) k4(c6,t7)
//         k5(c5,t6) k6(c4,t5) k7(c3,t4) k8(c2,t3) k9(c1,t2)
__device__ __forceinline__ void ring_b_d(u64* v0, u64* v1, Xch& X,
                                         const float2* __restrict__ a0,
                                         const float2* __restrict__ a1,
                                         float sgn, int lane, int tid, bool rev)
{
    if (!rev) {
        { bool act = lane & 1;
          crx_shfl(v0, 1, act, CC0(0), SS0(0)); crx_shfl(v1, 1, act, CC1(0), SS1(0)); }
        { bool act = (tid >> 6) & 1;
          crx_shfl(v0, 0, act, CC0(1), SS0(1)); crx_shfl(v1, 0, act, CC1(1), SS1(1)); }
        crx_warp_tgt_d(v0, v1, X, 1, (tid >> 5) & 1, CC0(2), SS0(2), CC1(2), SS1(2));
        crx_rw_d(v0, v1, X, 0, CC0(3), SS0(3), CC1(3), SS1(3));
        crx_rr<1,2>(v0, CC0(4), SS0(4)); crx_rr<1,2>(v1, CC1(4), SS1(4));
        crx_rr<0,1>(v0, CC0(5), SS0(5)); crx_rr<0,1>(v1, CC1(5), SS1(5));
        { bool act = (lane >> 4) & 1;
          crx_reg_tgt<0>(v0, act, CC0(6), SS0(6)); crx_reg_tgt<0>(v1, act, CC1(6), SS1(6)); }
        #pragma unroll 1
        for (int j = 7; j <= 9; ++j) {
            int pt = 11 - j;
            bool act = (lane >> (10 - j)) & 1;
            crx_shfl(v0, pt, act, CC0(j), SS0(j));
            crx_shfl(v1, pt, act, CC1(j), SS1(j));
        }
    } else {
        #pragma unroll 1
        for (int j = 9; j >= 7; --j) {
            int pt = 11 - j;
            bool act = (lane >> (10 - j)) & 1;
            crx_shfl(v0, pt, act, CC0(j), SS0(j));
            crx_shfl(v1, pt, act, CC1(j), SS1(j));
        }
        { bool act = (lane >> 4) & 1;
          crx_reg_tgt<0>(v0, act, CC0(6), SS0(6)); crx_reg_tgt<0>(v1, act, CC1(6), SS1(6)); }
        crx_rr<0,1>(v0, CC0(5), SS0(5)); crx_rr<0,1>(v1, CC1(5), SS1(5));
        crx_rr<1,2>(v0, CC0(4), SS0(4)); crx_rr<1,2>(v1, CC1(4), SS1(4));
        crx_rw_d(v0, v1, X, 0, CC0(3), SS0(3), CC1(3), SS1(3));
        crx_warp_tgt_d(v0, v1, X, 1, (tid >> 5) & 1, CC0(2), SS0(2), CC1(2), SS1(2));
        { bool act = (tid >> 6) & 1;
          crx_shfl(v0, 0, act, CC0(1), SS0(1)); crx_shfl(v1, 0, act, CC1(1), SS1(1)); }
        { bool act = lane & 1;
          crx_shfl(v0, 1, act, CC0(0), SS0(0)); crx_shfl(v1, 1, act, CC1(0), SS1(0)); }
    }
}

// ------------------------------------------------------------- select -------
// Each CTA processes blocks c0 = 2*blockIdx and c1 = c0+1.
__global__ void __launch_bounds__(128) k_sel_f(int nlayers, int useQff, int initFlag)
{
    int blk = blockIdx.x;
    int c0 = blk*2, c1 = c0 + 1;
    int tid = threadIdx.x;
    int lane = tid & 31;
    const float sgn = 1.f;
    __shared__ float2 sang[160];
    __shared__ u64 xbuf[4096];
    const float2 *a0base, *a1base;
    if (useQff) {
        if (tid < QROTS) sang[tid] = g_qff[tid];
        a0base = sang; a1base = sang;
    } else {
        int ntot = nlayers * 40;
        if (tid < ntot)      sang[tid]      = g_csn[c0*NROTS + tid];
        if (tid < ntot)      sang[80 + tid] = g_csn[c1*NROTS + tid];
        a0base = sang; a1base = sang + 80;
    }
    __syncthreads();

    Xch X{xbuf, 0, tid};
    u64 v0[8], v1[8];
    u64* gb0 = G_STATEU + ((size_t)c0 << 10);
    u64* gb1 = G_STATEU + ((size_t)c1 << 10);
    int base = (tid >> 5) * 256 + lane;
    if (initFlag) {
        #pragma unroll
        for (int q = 0; q < 8; ++q) { v0[q] = 0ull; v1[q] = 0ull; }
        if (tid == 0) {
            float2 f0 = g_v0[c0 & 15]; v0[0] = pk2(f0.x, f0.y);
            float2 f1 = g_v0[c1 & 15]; v1[0] = pk2(f1.x, f1.y);
        }
    } else {
        #pragma unroll
        for (int q = 0; q < 8; ++q) { v0[q] = gb0[base + q*32]; v1[q] = gb1[base + q*32]; }
    }

    #pragma unroll 1
    for (int l = 0; l < nlayers; ++l) {
        const float2* a0 = a0base + 40*l;
        const float2* a1 = a1base + 40*l;
        ry_all_d(v0, v1, X, a0, a1, sgn, lane);
        ring_a_d(v0, v1, X, a0 + 10, a1 + 10, sgn, lane, tid, false);
        ry_all_d(v0, v1, X, a0 + 20, a1 + 20, sgn, lane);
        ring_b_d(v0, v1, X, a0 + 30, a1 + 30, sgn, lane, tid, false);
    }

    #pragma unroll
    for (int q = 0; q < 8; ++q) { gb0[base + q*32] = v0[q]; gb1[base + q*32] = v1[q]; }
}

__global__ void __launch_bounds__(128) k_sel_a(int nlayers)
{
    int blk = blockIdx.x;
    int c0 = blk*2, c1 = c0 + 1;
    int tid = threadIdx.x;
    int lane = tid & 31;
    const float sgn = -1.f;
    __shared__ float2 sang[160];
    __shared__ u64 xbuf[4096];
    {
        int ntot = nlayers * 40;
        if (tid < ntot)      sang[tid]      = g_csn[c0*NROTS + tid];
        if (tid < ntot)      sang[80 + tid] = g_csn[c1*NROTS + tid];
    }
    __syncthreads();

    Xch X{xbuf, 0, tid};
    u64 v0[8], v1[8];
    u64* gb0 = G_STATEU + ((size_t)c0 << 10);
    u64* gb1 = G_STATEU + ((size_t)c1 << 10);
    int base = (tid >> 5) * 256 + lane;
    #pragma unroll
    for (int q = 0; q < 8; ++q) { v0[q] = gb0[base + q*32]; v1[q] = gb1[base + q*32]; }

    #pragma unroll 1
    for (int l = nlayers - 1; l >= 0; --l) {
        const float2* a0 = sang + 40*l;
        const float2* a1 = sang + 80 + 40*l;
        ring_b_d(v0, v1, X, a0 + 30, a1 + 30, sgn, lane, tid, true);
        ry_all_d(v0, v1, X, a0 + 20, a1 + 20, sgn, lane);
        ring_a_d(v0, v1, X, a0 + 10, a1 + 10, sgn, lane, tid, true);
        ry_all_d(v0, v1, X, a0, a1, sgn, lane);
    }

    #pragma unroll
    for (int q = 0; q < 8; ++q) { gb0[base + q*32] = v0[q]; gb1[base + q*32] = v1[q]; }
}

// ---------------------------------------------------------- ancilla mat -----
// 1 thread = 1 amplitude. CTA = 512 threads = (16 a) x (32 s).
__global__ void __launch_bounds__(512) k_anc(int mi)
{
    __shared__ u64 sx[16*32];
    __shared__ u64 sM[256];
    int tid = threadIdx.x;
    int a  = tid >> 5;
    int sj = tid & 31;
    int blk = blockIdx.x;
    int b = blk >> 5;
    int s = ((blk & 31) << 5) + sj;

    size_t idx = (((size_t)(b*16 + a)) << 10) + s;
    u64 xv = G_STATEU[idx];
    sx[a*32 + sj] = xv;
    if (tid < 256) sM[tid] = ((const u64*)g_M[mi])[tid];
    __syncthreads();

    u64 acc = 0ull;
    #pragma unroll
    for (int k = 0; k < 16; ++k) {
        float2 m = upk(sM[a*16 + k]);
        u64 x2 = sx[k*32 + sj];
        acc = fma2(pk2(m.x, m.x), x2, acc);
        acc = fma2(pk2(-m.y, m.y), swap2(x2), acc);
    }
    G_STATEU[idx] = acc;
}

// ------------------------------------------------- expvals + output GEMM ----
__global__ void __launch_bounds__(640) k_exp_out(const float* __restrict__ W_out,
                                                 const float* __restrict__ b_out,
                                                 float* __restrict__ out)
{
    int b = blockIdx.x;
    int tid = threadIdx.x, w = tid >> 5, lane = tid & 31;
    const float2* st = G_STATE + ((size_t)b << 14);
    __shared__ float red[20][3];
    __shared__ float ex[30];

    {
        int qi = w % 10, half = w / 10;
        int p = 9 - qi;
        float cr = 0.f, ci = 0.f, zz = 0.f;
        int start = half * 4096 + lane;
        #pragma unroll 4
        for (int pk_ = start; pk_ < start - lane + 4096; pk_ += 32) {
            int a = pk_ >> 9, m = pk_ & 511;
            int s0 = ((m >> p) << (p+1)) | (m & ((1 << p) - 1));
            int f0 = (a << 10) | s0;
            float2 a0 = st[f0];
            float2 a1 = st[f0 | (1 << p)];
            cr += a0.x*a1.x + a0.y*a1.y;
            ci += a0.x*a1.y - a0.y*a1.x;
            zz += (a0.x*a0.x + a0.y*a0.y) - (a1.x*a1.x + a1.y*a1.y);
        }
        #pragma unroll
        for (int off = 16; off; off >>= 1) {
            cr += __shfl_down_sync(0xffffffffu, cr, off);
            ci += __shfl_down_sync(0xffffffffu, ci, off);
            zz += __shfl_down_sync(0xffffffffu, zz, off);
        }
        if (lane == 0) { red[w][0] = cr; red[w][1] = ci; red[w][2] = zz; }
    }
    __syncthreads();
    if (tid < 10) {
        ex[tid]      = 2.f*(red[tid][0] + red[tid+10][0]);
        ex[10 + tid] = 2.f*(red[tid][1] + red[tid+10][1]);
        ex[20 + tid] =      red[tid][2] + red[tid+10][2];
    }
    __syncthreads();
    if (tid < ODIM) {
        float acc = b_out[tid];
        #pragma unroll
        for (int j = 0; j < 30; ++j) acc += W_out[tid*30 + j] * ex[j];
        out[b*ODIM + tid] = acc;
    }
}

// ------------------------------------------------------------ launch --------
extern "C" void kernel_launch(void* const* d_in, const int* in_sizes, int n_in,
                              void* d_out, int out_size)
{
    const float* x       = (const float*)d_in[0];
    const float* W_fp    = (const float*)d_in[1];
    const float* b_fp    = (const float*)d_in[2];
    const float* prep_p  = (const float*)d_in[3];
    const float* sig_ang = (const float*)d_in[4];
    const float* qff_p   = (const float*)d_in[5];
    const float* W_out   = (const float*)d_in[6];
    const float* b_out   = (const float*)d_in[7];
    float* out = (float*)d_out;

    k_pre<<<257, 256>>>(x, W_fp, b_fp, prep_p, sig_ang, qff_p);

    k_sel_f<<<128, 128>>>(2, 0, 1);   // k=0 forward (fused init)
    k_anc<<<512, 512>>>(0);
    k_sel_a<<<128, 128>>>(2);         // k=1 adjoint
    k_anc<<<512, 512>>>(1);
    k_sel_f<<<128, 128>>>(2, 0, 0);   // k=2 forward
    k_anc<<<512, 512>>>(2);

    k_sel_f<<<128, 128>>>(1, 1, 0);   // qff layer

    k_exp_out<<<Bsz, 640>>>(W_out, b_out, out);
}

// round 12
// speedup vs baseline: 1.0096x; 1.0096x over previous
#include <cuda_runtime.h>
#include <math.h>

#define Bsz 16
#define Tn 16
#define FDIM 64
#define ODIM 8
#define NQ 10
#define NA 4
#define NROTS 80
#define QROTS 40
#define NS 1024
#define NANC 16
#define STATE_PER_B (NS*NANC)
#define TOTAL_AMPS (Bsz*STATE_PER_B)
#define NCTA 256

typedef unsigned long long u64;

__device__ float4 g_state4[TOTAL_AMPS/2];
#define G_STATE  ((float2*)g_state4)
#define G_STATEU ((u64*)g_state4)
__device__ float2 g_csn[Bsz*Tn*NROTS];
__device__ float2 g_qff[QROTS];
__device__ float2 g_M[3][256];
__device__ float2 g_v0[16];
__device__ float  g_ex[Bsz*30];
__device__ unsigned g_count;
__device__ unsigned g_sense;

// ------------------------------------------------------- packed f32x2 ops ---
__device__ __forceinline__ u64 pk2(float x, float y) {
    u64 r; asm("mov.b64 %0, {%1, %2};" : "=l"(r) : "f"(x), "f"(y)); return r;
}
__device__ __forceinline__ float2 upk(u64 a) {
    float2 f; asm("mov.b64 {%0, %1}, %2;" : "=f"(f.x), "=f"(f.y) : "l"(a)); return f;
}
__device__ __forceinline__ u64 mul2(u64 a, u64 b) {
    u64 d; asm("mul.rn.f32x2 %0, %1, %2;" : "=l"(d) : "l"(a), "l"(b)); return d;
}
__device__ __forceinline__ u64 fma2(u64 a, u64 b, u64 c) {
    u64 d; asm("fma.rn.f32x2 %0, %1, %2, %3;" : "=l"(d) : "l"(a), "l"(b), "l"(c)); return d;
}
__device__ __forceinline__ u64 swap2(u64 a) {
    float2 f = upk(a); return pk2(f.y, f.x);
}

// -------------------------------------------------------- global barrier ----
__device__ __forceinline__ void gbar(unsigned target)
{
    __syncthreads();
    if (threadIdx.x == 0) {
        __threadfence();
        unsigned arrived = atomicAdd(&g_count, 1u) + 1u;
        if (arrived == (unsigned)NCTA) {
            g_count = 0u;
            __threadfence();
            atomicExch(&g_sense, target);
        } else {
            while ((int)(*(volatile unsigned*)&g_sense - target) < 0) { }
        }
        __threadfence();
    }
    __syncthreads();
}

// ------------------------------------------------------- gate primitives ----
// layout: amplitude s: lane = s[4:0], reg = s[7:5] (8 u64/lane), warp = s[9:8].

template<int PB>
__device__ __forceinline__ void ry_reg(u64* v, float cc, float ss)
{
    u64 cc2 = pk2(cc, cc), ss2 = pk2(ss, ss), nss2 = pk2(-ss, -ss);
    #pragma unroll
    for (int m = 0; m < 4; ++m) {
        int i0 = ((m >> PB) << (PB+1)) | (m & ((1 << PB) - 1));
        int i1 = i0 | (1 << PB);
        u64 a0 = v[i0], a1 = v[i1];
        v[i0] = fma2(cc2, a0, mul2(nss2, a1));
        v[i1] = fma2(cc2, a1, mul2(ss2, a0));
    }
}

__device__ __forceinline__ void ry_lane(u64* v, int pl, float cc, float ss, int lane)
{
    float sg = ((lane >> pl) & 1) ? ss : -ss;
    u64 cc2 = pk2(cc, cc), sg2 = pk2(sg, sg);
    int mk = 1 << pl;
    #pragma unroll
    for (int q = 0; q < 8; ++q) {
        float2 f = upk(v[q]);
        float px = __shfl_xor_sync(0xffffffffu, f.x, mk);
        float py = __shfl_xor_sync(0xffffffffu, f.y, mk);
        v[q] = fma2(cc2, v[q], mul2(sg2, pk2(px, py)));
    }
}

template<int PCB, int PTB>
__device__ __forceinline__ void crx_rr(u64* v, float cc, float ss)
{
    u64 cc2 = pk2(cc, cc), ssv2 = pk2(ss, -ss);
    #pragma unroll
    for (int i = 0; i < 8; ++i) {
        if ((((i >> PCB) & 1) == 1) && (((i >> PTB) & 1) == 0)) {
            int i1 = i | (1 << PTB);
            u64 a0 = v[i], a1 = v[i1];
            v[i]  = fma2(cc2, a0, mul2(ssv2, swap2(a1)));
            v[i1] = fma2(cc2, a1, mul2(ssv2, swap2(a0)));
        }
    }
}

__device__ __forceinline__ void crx_shfl(u64* v, int pt, bool act, float cc, float ss)
{
    float ccl = act ? cc : 1.f, ssl = act ? ss : 0.f;
    u64 cc2 = pk2(ccl, ccl), ssv2 = pk2(ssl, -ssl);
    int mk = 1 << pt;
    #pragma unroll
    for (int q = 0; q < 8; ++q) {
        float2 f = upk(v[q]);
        float px = __shfl_xor_sync(0xffffffffu, f.x, mk);
        float py = __shfl_xor_sync(0xffffffffu, f.y, mk);
        v[q] = fma2(cc2, v[q], mul2(ssv2, pk2(py, px)));
    }
}

template<int PCB>
__device__ __forceinline__ void crx_rl(u64* v, int pt, float cc, float ss)
{
    u64 cc2 = pk2(cc, cc), ssv2 = pk2(ss, -ss);
    int mk = 1 << pt;
    #pragma unroll
    for (int q = 0; q < 8; ++q) {
        if ((q >> PCB) & 1) {
            float2 f = upk(v[q]);
            float px = __shfl_xor_sync(0xffffffffu, f.x, mk);
            float py = __shfl_xor_sync(0xffffffffu, f.y, mk);
            v[q] = fma2(cc2, v[q], mul2(ssv2, pk2(py, px)));
        }
    }
}

template<int PTB>
__device__ __forceinline__ void crx_reg_tgt(u64* v, bool act, float cc, float ss)
{
    float ccl = act ? cc : 1.f, ssl = act ? ss : 0.f;
    u64 cc2 = pk2(ccl, ccl), ssv2 = pk2(ssl, -ssl);
    #pragma unroll
    for (int m = 0; m < 4; ++m) {
        int i0 = ((m >> PTB) << (PTB+1)) | (m & ((1 << PTB) - 1));
        int i1 = i0 | (1 << PTB);
        u64 a0 = v[i0], a1 = v[i1];
        v[i0] = fma2(cc2, a0, mul2(ssv2, swap2(a1)));
        v[i1] = fma2(cc2, a1, mul2(ssv2, swap2(a0)));
    }
}

// ----- cross-warp exchange gates (double-buffered smem, 1 bar each) ---------
struct Xch {
    u64* base; int tog; int tid;
    __device__ __forceinline__ u64* next() { u64* p = base + ((tog & 1) << 10); ++tog; return p; }
};

__device__ __forceinline__ void ry_warp(u64* v, Xch& X, int wb, float cc, float ss)
{
    u64* b = X.next();
    int tid = X.tid, xv = 32 << wb;
    #pragma unroll
    for (int i = 0; i < 8; ++i) b[i*128 + tid] = v[i];
    __syncthreads();
    float sg = ((tid >> (5 + wb)) & 1) ? ss : -ss;
    u64 cc2 = pk2(cc, cc), sg2 = pk2(sg, sg);
    #pragma unroll
    for (int i = 0; i < 8; ++i)
        v[i] = fma2(cc2, v[i], mul2(sg2, b[i*128 + (tid ^ xv)]));
}

__device__ __forceinline__ void crx_warp_tgt(u64* v, Xch& X, int twb, bool act, float cc, float ss)
{
    u64* b = X.next();
    int tid = X.tid, xv = 32 << twb;
    #pragma unroll
    for (int i = 0; i < 8; ++i) b[i*128 + tid] = v[i];
    __syncthreads();
    float ccl = act ? cc : 1.f, ssl = act ? ss : 0.f;
    u64 cc2 = pk2(ccl, ccl), ssv2 = pk2(ssl, -ssl);
    #pragma unroll
    for (int i = 0; i < 8; ++i)
        v[i] = fma2(cc2, v[i], mul2(ssv2, swap2(b[i*128 + (tid ^ xv)])));
}

__device__ __forceinline__ void crx_rw(u64* v, Xch& X, int twb, float cc, float ss)
{
    u64* b = X.next();
    int tid = X.tid, xv = 32 << twb;
    #pragma unroll
    for (int i = 0; i < 4; ++i) b[i*128 + tid] = v[4 + i];
    __syncthreads();
    u64 cc2 = pk2(cc, cc), ssv2 = pk2(ss, -ss);
    #pragma unroll
    for (int i = 0; i < 4; ++i)
        v[4 + i] = fma2(cc2, v[4 + i], mul2(ssv2, swap2(b[i*128 + (tid ^ xv)])));
}

// -------------------------------------------------------- layer pieces ------
#define SS(A) (sgn*(A).y)

__device__ __forceinline__ void ry_all(u64* v, Xch& X, const float2* __restrict__ ang,
                                       float sgn, int lane)
{
    ry_warp(v, X, 1, ang[0].x, SS(ang[0]));      // q0 -> bit9 (wb1)
    ry_warp(v, X, 0, ang[1].x, SS(ang[1]));      // q1 -> bit8 (wb0)
    ry_reg<2>(v, ang[2].x, SS(ang[2]));          // q2 -> bit7
    ry_reg<1>(v, ang[3].x, SS(ang[3]));
    ry_reg<0>(v, ang[4].x, SS(ang[4]));
    #pragma unroll 1
    for (int pl = 4; pl >= 0; --pl) {
        float2 cs = ang[9 - pl];
        ry_lane(v, pl, cs.x, sgn*cs.y, lane);
    }
}

// ring A: gate k = (ctrl bit k, tgt bit k-1 mod 10), angle ang[k]
__device__ __forceinline__ void ring_a(u64* v, Xch& X, const float2* __restrict__ ang,
                                       float sgn, int lane, int tid, bool rev)
{
    if (!rev) {
        crx_warp_tgt(v, X, 1, lane & 1, ang[0].x, SS(ang[0]));
        crx_shfl(v, 0, (lane >> 1) & 1, ang[1].x, SS(ang[1]));
        crx_shfl(v, 1, (lane >> 2) & 1, ang[2].x, SS(ang[2]));
        crx_shfl(v, 2, (lane >> 3) & 1, ang[3].x, SS(ang[3]));
        crx_shfl(v, 3, (lane >> 4) & 1, ang[4].x, SS(ang[4]));
        crx_rl<0>(v, 4, ang[5].x, SS(ang[5]));
        crx_rr<1,0>(v, ang[6].x, SS(ang[6]));
        crx_rr<2,1>(v, ang[7].x, SS(ang[7]));
        crx_reg_tgt<2>(v, (tid >> 5) & 1, ang[8].x, SS(ang[8]));
        crx_warp_tgt(v, X, 0, (tid >> 6) & 1, ang[9].x, SS(ang[9]));
    } else {
        crx_warp_tgt(v, X, 0, (tid >> 6) & 1, ang[9].x, SS(ang[9]));
        crx_reg_tgt<2>(v, (tid >> 5) & 1, ang[8].x, SS(ang[8]));
        crx_rr<2,1>(v, ang[7].x, SS(ang[7]));
        crx_rr<1,0>(v, ang[6].x, SS(ang[6]));
        crx_rl<0>(v, 4, ang[5].x, SS(ang[5]));
        crx_shfl(v, 3, (lane >> 4) & 1, ang[4].x, SS(ang[4]));
        crx_shfl(v, 2, (lane >> 3) & 1, ang[3].x, SS(ang[3]));
        crx_shfl(v, 1, (lane >> 2) & 1, ang[2].x, SS(ang[2]));
        crx_shfl(v, 0, (lane >> 1) & 1, ang[1].x, SS(ang[1]));
        crx_warp_tgt(v, X, 1, lane & 1, ang[0].x, SS(ang[0]));
    }
}

// ring B: k0(c0,t1) k1(c9,t0) k2(c8,t9) k3(c7,t8) k4(c6,t7)
//         k5(c5,t6) k6(c4,t5) k7(c3,t4) k8(c2,t3) k9(c1,t2)
__device__ __forceinline__ void ring_b(u64* v, Xch& X, const float2* __restrict__ ang,
                                       float sgn, int lane, int tid, bool rev)
{
    if (!rev) {
        crx_shfl(v, 1, lane & 1, ang[0].x, SS(ang[0]));
        crx_shfl(v, 0, (tid >> 6) & 1, ang[1].x, SS(ang[1]));
        crx_warp_tgt(v, X, 1, (tid >> 5) & 1, ang[2].x, SS(ang[2]));
        crx_rw(v, X, 0, ang[3].x, SS(ang[3]));
        crx_rr<1,2>(v, ang[4].x, SS(ang[4]));
        crx_rr<0,1>(v, ang[5].x, SS(ang[5]));
        crx_reg_tgt<0>(v, (lane >> 4) & 1, ang[6].x, SS(ang[6]));
        crx_shfl(v, 4, (lane >> 3) & 1, ang[7].x, SS(ang[7]));
        crx_shfl(v, 3, (lane >> 2) & 1, ang[8].x, SS(ang[8]));
        crx_shfl(v, 2, (lane >> 1) & 1, ang[9].x, SS(ang[9]));
    } else {
        crx_shfl(v, 2, (lane >> 1) & 1, ang[9].x, SS(ang[9]));
        crx_shfl(v, 3, (lane >> 2) & 1, ang[8].x, SS(ang[8]));
        crx_shfl(v, 4, (lane >> 3) & 1, ang[7].x, SS(ang[7]));
        crx_reg_tgt<0>(v, (lane >> 4) & 1, ang[6].x, SS(ang[6]));
        crx_rr<0,1>(v, ang[5].x, SS(ang[5]));
        crx_rr<1,2>(v, ang[4].x, SS(ang[4]));
        crx_rw(v, X, 0, ang[3].x, SS(ang[3]));
        crx_warp_tgt(v, X, 1, (tid >> 5) & 1, ang[2].x, SS(ang[2]));
        crx_shfl(v, 0, (tid >> 6) & 1, ang[1].x, SS(ang[1]));
        crx_shfl(v, 1, lane & 1, ang[0].x, SS(ang[0]));
    }
}

// ---------------------------------------------------------- select phase ----
__device__ void sel_phase(int c, int tid, int lane, u64* xbuf, float2* sang,
                          int nlayers, int useQff, int adjoint, int init)
{
    if (useQff) { if (tid < QROTS) sang[tid] = g_qff[tid]; }
    else { int ntot = nlayers * 40; if (tid < ntot) sang[tid] = g_csn[c*NROTS + tid]; }
    __syncthreads();

    Xch X{xbuf, 0, tid};
    u64 v[8];
    u64* gb = G_STATEU + ((size_t)c << 10);
    int base = (tid >> 5) * 256 + lane;
    if (init) {
        #pragma unroll
        for (int q = 0; q < 8; ++q) v[q] = 0ull;
        if (tid == 0) { float2 f = g_v0[c & 15]; v[0] = pk2(f.x, f.y); }
    } else {
        #pragma unroll
        for (int q = 0; q < 8; ++q) v[q] = gb[base + q*32];
    }

    if (!adjoint) {
        const float sgn = 1.f;
        #pragma unroll 1
        for (int l = 0; l < nlayers; ++l) {
            const float2* a = sang + 40*l;
            ry_all(v, X, a, sgn, lane);
            ring_a(v, X, a + 10, sgn, lane, tid, false);
            ry_all(v, X, a + 20, sgn, lane);
            ring_b(v, X, a + 30, sgn, lane, tid, false);
        }
    } else {
        const float sgn = -1.f;
        #pragma unroll 1
        for (int l = nlayers - 1; l >= 0; --l) {
            const float2* a = sang + 40*l;
            ring_b(v, X, a + 30, sgn, lane, tid, true);
            ry_all(v, X, a + 20, sgn, lane);
            ring_a(v, X, a + 10, sgn, lane, tid, true);
            ry_all(v, X, a, sgn, lane);
        }
    }

    #pragma unroll
    for (int q = 0; q < 8; ++q) gb[base + q*32] = v[q];
}

// ------------------------------------------------------------- anc phase ----
// CTA c = (b = c>>4, s-chunk = c&15, 64 s values). Tile 16a x 64s in smem.
__device__ void anc_phase(int c, int tid, int mi, u64* pool)
{
    u64* tile = pool;           // 1024 u64
    u64* sM   = pool + 1024;    // 256 u64
    int b = c >> 4, sc = c & 15;
    sM[tid]       = ((const u64*)g_M[mi])[tid];
    sM[128 + tid] = ((const u64*)g_M[mi])[128 + tid];
    size_t sb = ((size_t)b << 14) + ((size_t)sc << 6);
    #pragma unroll
    for (int i = 0; i < 8; ++i) {
        int idx = i*128 + tid;
        int a = idx >> 6, sj = idx & 63;
        tile[idx] = G_STATEU[sb + ((size_t)a << 10) + sj];
    }
    __syncthreads();
    #pragma unroll
    for (int i = 0; i < 8; ++i) {
        int idx = i*128 + tid;
        int a = idx >> 6, sj = idx & 63;
        u64 acc = 0ull;
        #pragma unroll
        for (int k = 0; k < 16; ++k) {
            float2 m = upk(sM[a*16 + k]);
            u64 xv = tile[k*64 + sj];
            acc = fma2(pk2(m.x, m.x), xv, acc);
            acc = fma2(pk2(-m.y, m.y), swap2(xv), acc);
        }
        G_STATEU[sb + ((size_t)a << 10) + sj] = acc;
    }
}

// ------------------------------------------------------------- exp phase ----
__device__ void exp_phase(int c, int tid, float* sred)
{
    if (c >= 160) return;
    int b = c / 10, qi = c - 10*b;
    int p = 9 - qi;
    const float2* st = G_STATE + ((size_t)b << 14);
    float cr = 0.f, ci = 0.f, zz = 0.f;
    #pragma unroll 4
    for (int pk_ = tid; pk_ < 8192; pk_ += 128) {
        int a = pk_ >> 9, m = pk_ & 511;
        int s0 = ((m >> p) << (p+1)) | (m & ((1 << p) - 1));
        int f0 = (a << 10) | s0;
        float2 a0 = st[f0];
        float2 a1 = st[f0 | (1 << p)];
        cr += a0.x*a1.x + a0.y*a1.y;
        ci += a0.x*a1.y - a0.y*a1.x;
        zz += (a0.x*a0.x + a0.y*a0.y) - (a1.x*a1.x + a1.y*a1.y);
    }
    #pragma unroll
    for (int off = 16; off; off >>= 1) {
        cr += __shfl_down_sync(0xffffffffu, cr, off);
        ci += __shfl_down_sync(0xffffffffu, ci, off);
        zz += __shfl_down_sync(0xffffffffu, zz, off);
    }
    int w = tid >> 5;
    if ((tid & 31) == 0) { sred[w*3+0] = cr; sred[w*3+1] = ci; sred[w*3+2] = zz; }
    __syncthreads();
    if (tid == 0) {
        float A = 0.f, Bv = 0.f, C = 0.f;
        #pragma unroll
        for (int ww = 0; ww < 4; ++ww) { A += sred[ww*3]; Bv += sred[ww*3+1]; C += sred[ww*3+2]; }
        g_ex[b*30 + qi]      = 2.f * A;
        g_ex[b*30 + 10 + qi] = 2.f * Bv;
        g_ex[b*30 + 20 + qi] = C;
    }
}

// -------------------------------------------------------------- mega --------
__global__ void __launch_bounds__(128, 2) mega(
    const float* __restrict__ x,
    const float* __restrict__ Wfp,
    const float* __restrict__ bfp,
    const float* __restrict__ prep_p,
    const float* __restrict__ sig_ang,
    const float* __restrict__ qff_p,
    const float* __restrict__ W_out,
    const float* __restrict__ b_out,
    float* __restrict__ out)
{
    int c = blockIdx.x;
    int tid = threadIdx.x;
    int lane = tid & 31;
    __shared__ u64 xbuf[2048];
    __shared__ float2 sang[80];
    __shared__ float sred[12];
    __shared__ unsigned s_base;
    if (tid == 0) s_base = *(volatile unsigned*)&g_sense;
    __syncthreads();
    unsigned gen = s_base;

    // ----- P0: angles for (b,t) = c; CTA0 also does setup -----
    {
        float* h = (float*)xbuf;                       // 64 floats
        int b = c >> 4, t = c & 15;
        if (tid < 64) {
            int f = tid;
            int k = f >> 1;
            float div = expf((float)(2*k) * (-logf(10000.0f) / 64.0f));
            float arg = (float)t * div;
            float pe = (f & 1) ? cosf(arg) : sinf(arg);
            h[f] = x[(b*64 + f)*16 + t] + pe;
        }
        __syncthreads();
        if (tid < NROTS) {
            float acc = bfp[tid];
            const float* w = Wfp + tid*64;
            #pragma unroll
            for (int f = 0; f < 64; ++f) acc += h[f]*w[f];
            float sg = 1.0f / (1.0f + expf(-acc));
            float sn, cs;
            sincosf(3.14159265358979323846f * sg, &sn, &cs);
            g_csn[c*NROTS + tid] = make_float2(cs, sn);
        }
        if (c == 0) {
            float2 (*sU)[16] = (float2(*)[16])(xbuf + 64);   // 2KB, disjoint from h
            if (tid < 16) {
                float2 v[16];
                #pragma unroll
                for (int i = 0; i < 16; ++i) v[i] = make_float2(0.f, 0.f);
                v[tid] = make_float2(1.f, 0.f);
                for (int ly = 0; ly < 4; ++ly) {
                    for (int qi = 0; qi < 4; ++qi) {
                        int p = 3 - qi;
                        float thy = prep_p[(ly*4 + qi)*2 + 0];
                        float thz = prep_p[(ly*4 + qi)*2 + 1];
                        float cth, sth;
                        sincosf(0.5f*thy, &sth, &cth);
                        for (int m = 0; m < 8; ++m) {
                            int i0 = ((m >> p) << (p+1)) | (m & ((1 << p) - 1));
                            int i1 = i0 | (1 << p);
                            float2 a0 = v[i0], a1 = v[i1];
                            v[i0] = make_float2(cth*a0.x - sth*a1.x, cth*a0.y - sth*a1.y);
                            v[i1] = make_float2(sth*a0.x + cth*a1.x, sth*a0.y + cth*a1.y);
                        }
                        float cz, sz;
                        sincosf(0.5f*thz, &sz, &cz);
                        for (int i = 0; i < 16; ++i) {
                            float im = ((i >> p) & 1) ? sz : -sz;
                            float2 a = v[i];
                            v[i] = make_float2(cz*a.x - im*a.y, cz*a.y + im*a.x);
                        }
                    }
                    for (int i = 0; i < 3; ++i) {
                        int pc = 3 - i, pt = 2 - i;
                        for (int idx = 0; idx < 16; ++idx) {
                            if (((idx >> pc) & 1) == 1 && ((idx >> pt) & 1) == 0) {
                                int j = idx | (1 << pt);
                                float2 tmp = v[idx]; v[idx] = v[j]; v[j] = tmp;
                            }
                        }
                    }
                }
                #pragma unroll
                for (int r = 0; r < 16; ++r) sU[r][tid] = v[r];
            }
            __syncthreads();
            if (tid < 16) {
                float c0, s0;
                sincosf(sig_ang[0], &s0, &c0);
                float2 u = sU[tid][0];
                g_v0[tid] = make_float2(c0*u.x - s0*u.y, c0*u.y + s0*u.x);
            }
            if (tid >= 64 && tid < 64 + QROTS) {
                float cq, sq;
                sincosf(0.5f * qff_p[tid - 64], &sq, &cq);
                g_qff[tid - 64] = make_float2(cq, sq);
            }
            #pragma unroll 1
            for (int half = 0; half < 2; ++half) {
                int idx = half*128 + tid;
                int j = idx >> 4, k = idx & 15;
                for (int m = 0; m < 2; ++m) {
                    float cp, sp;
                    sincosf(sig_ang[m+1], &sp, &cp);
                    float2 acc = make_float2(0.f, 0.f);
                    #pragma unroll
                    for (int a = 0; a < 16; ++a) {
                        float2 uja = sU[j][a];
                        float2 uka = sU[k][a];
                        float dr = cp, di = (a == 0) ? sp : -sp;
                        float2 dc = make_float2(dr*uka.x + di*uka.y, di*uka.x - dr*uka.y);
                        acc.x += uja.x*dc.x - uja.y*dc.y;
                        acc.y += uja.x*dc.y + uja.y*dc.x;
                    }
                    g_M[m][j*16 + k] = acc;
                }
                float cp, sp;
                sincosf(sig_ang[3], &sp, &cp);
                float dr = cp, di = (j == 0) ? sp : -sp;
                float2 u2 = sU[k][j];
                g_M[2][j*16 + k] = make_float2(dr*u2.x + di*u2.y, di*u2.x - dr*u2.y);
            }
        }
    }
    gbar(gen + 1);

    sel_phase(c, tid, lane, xbuf, sang, 2, 0, 0, 1);   // k=0 forward (init)
    gbar(gen + 2);
    anc_phase(c, tid, 0, xbuf);
    gbar(gen + 3);
    sel_phase(c, tid, lane, xbuf, sang, 2, 0, 1, 0);   // k=1 adjoint
    gbar(gen + 4);
    anc_phase(c, tid, 1, xbuf);
    gbar(gen + 5);
    sel_phase(c, tid, lane, xbuf, sang, 2, 0, 0, 0);   // k=2 forward
    gbar(gen + 6);
    anc_phase(c, tid, 2, xbuf);
    gbar(gen + 7);
    sel_phase(c, tid, lane, xbuf, sang, 1, 1, 0, 0);   // qff layer
    gbar(gen + 8);
    exp_phase(c, tid, sred);
    gbar(gen + 9);
    if (c == 0) {
        int b = tid >> 3, o = tid & 7;
        float acc = b_out[o];
        #pragma unroll
        for (int j = 0; j < 30; ++j) acc += W_out[o*30 + j] * g_ex[b*30 + j];
        out[b*ODIM + o] = acc;
    }
}

// ------------------------------------------------------------ launch --------
extern "C" void kernel_launch(void* const* d_in, const int* in_sizes, int n_in,
                              void* d_out, int out_size)
{
    const float* x       = (const float*)d_in[0];
    const float* W_fp    = (const float*)d_in[1];
    const float* b_fp    = (const float*)d_in[2];
    const float* prep_p  = (const float*)d_in[3];
    const float* sig_ang = (const float*)d_in[4];
    const float* qff_p   = (const float*)d_in[5];
    const float* W_out   = (const float*)d_in[6];
    const float* b_out   = (const float*)d_in[7];
    float* out = (float*)d_out;

    mega<<<NCTA, 128>>>(x, W_fp, b_fp, prep_p, sig_ang, qff_p, W_out, b_out, out);
}

// round 13
// speedup vs baseline: 1.0981x; 1.0876x over previous
#include <cuda_runtime.h>
#include <math.h>

#define Bsz 16
#define Tn 16
#define FDIM 64
#define ODIM 8
#define NQ 10
#define NA 4
#define NROTS 80
#define QROTS 40
#define NS 1024
#define NANC 16
#define STATE_PER_B (NS*NANC)
#define TOTAL_AMPS (Bsz*STATE_PER_B)
#define NCTA 256

typedef unsigned long long u64;

__device__ float4 g_state4[TOTAL_AMPS/2];
#define G_STATE  ((float2*)g_state4)
#define G_STATEU ((u64*)g_state4)
__device__ float2 g_csn[Bsz*Tn*NROTS];
__device__ float2 g_qff[QROTS];
__device__ float2 g_M[3][256];
__device__ float2 g_v0[16];
__device__ float  g_ex[Bsz*30];
__device__ unsigned g_bcnt[16];
__device__ unsigned g_bsns[16];

// ------------------------------------------------------- packed f32x2 ops ---
__device__ __forceinline__ u64 pk2(float x, float y) {
    u64 r; asm("mov.b64 %0, {%1, %2};" : "=l"(r) : "f"(x), "f"(y)); return r;
}
__device__ __forceinline__ float2 upk(u64 a) {
    float2 f; asm("mov.b64 {%0, %1}, %2;" : "=f"(f.x), "=f"(f.y) : "l"(a)); return f;
}
__device__ __forceinline__ u64 mul2(u64 a, u64 b) {
    u64 d; asm("mul.rn.f32x2 %0, %1, %2;" : "=l"(d) : "l"(a), "l"(b)); return d;
}
__device__ __forceinline__ u64 fma2(u64 a, u64 b, u64 c) {
    u64 d; asm("fma.rn.f32x2 %0, %1, %2, %3;" : "=l"(d) : "l"(a), "l"(b), "l"(c)); return d;
}
__device__ __forceinline__ u64 swap2(u64 a) {
    float2 f = upk(a); return pk2(f.y, f.x);
}

// ----------------------------------------------------- per-batch barrier ----
__device__ __forceinline__ void bbar(int b, unsigned target)
{
    __syncthreads();
    if (threadIdx.x == 0) {
        __threadfence();
        unsigned arrived = atomicAdd(&g_bcnt[b], 1u) + 1u;
        if (arrived == 16u) {
            g_bcnt[b] = 0u;
            __threadfence();
            atomicExch(&g_bsns[b], target);
        } else {
            while ((int)(*(volatile unsigned*)&g_bsns[b] - target) < 0) { }
        }
        __threadfence();
    }
    __syncthreads();
}

// ------------------------------------------------------- gate primitives ----
// layout: amplitude s: lane = s[4:0], reg = s[7:5] (8 u64/lane), warp = s[9:8].

template<int PB>
__device__ __forceinline__ void ry_reg(u64* v, float cc, float ss)
{
    u64 cc2 = pk2(cc, cc), ss2 = pk2(ss, ss), nss2 = pk2(-ss, -ss);
    #pragma unroll
    for (int m = 0; m < 4; ++m) {
        int i0 = ((m >> PB) << (PB+1)) | (m & ((1 << PB) - 1));
        int i1 = i0 | (1 << PB);
        u64 a0 = v[i0], a1 = v[i1];
        v[i0] = fma2(cc2, a0, mul2(nss2, a1));
        v[i1] = fma2(cc2, a1, mul2(ss2, a0));
    }
}

__device__ __forceinline__ void ry_lane(u64* v, int pl, float cc, float ss, int lane)
{
    float sg = ((lane >> pl) & 1) ? ss : -ss;
    u64 cc2 = pk2(cc, cc), sg2 = pk2(sg, sg);
    int mk = 1 << pl;
    #pragma unroll
    for (int q = 0; q < 8; ++q) {
        float2 f = upk(v[q]);
        float px = __shfl_xor_sync(0xffffffffu, f.x, mk);
        float py = __shfl_xor_sync(0xffffffffu, f.y, mk);
        v[q] = fma2(cc2, v[q], mul2(sg2, pk2(px, py)));
    }
}

template<int PCB, int PTB>
__device__ __forceinline__ void crx_rr(u64* v, float cc, float ss)
{
    u64 cc2 = pk2(cc, cc), ssv2 = pk2(ss, -ss);
    #pragma unroll
    for (int i = 0; i < 8; ++i) {
        if ((((i >> PCB) & 1) == 1) && (((i >> PTB) & 1) == 0)) {
            int i1 = i | (1 << PTB);
            u64 a0 = v[i], a1 = v[i1];
            v[i]  = fma2(cc2, a0, mul2(ssv2, swap2(a1)));
            v[i1] = fma2(cc2, a1, mul2(ssv2, swap2(a0)));
        }
    }
}

__device__ __forceinline__ void crx_shfl(u64* v, int pt, bool act, float cc, float ss)
{
    float ccl = act ? cc : 1.f, ssl = act ? ss : 0.f;
    u64 cc2 = pk2(ccl, ccl), ssv2 = pk2(ssl, -ssl);
    int mk = 1 << pt;
    #pragma unroll
    for (int q = 0; q < 8; ++q) {
        float2 f = upk(v[q]);
        float px = __shfl_xor_sync(0xffffffffu, f.x, mk);
        float py = __shfl_xor_sync(0xffffffffu, f.y, mk);
        v[q] = fma2(cc2, v[q], mul2(ssv2, pk2(py, px)));
    }
}

template<int PCB>
__device__ __forceinline__ void crx_rl(u64* v, int pt, float cc, float ss)
{
    u64 cc2 = pk2(cc, cc), ssv2 = pk2(ss, -ss);
    int mk = 1 << pt;
    #pragma unroll
    for (int q = 0; q < 8; ++q) {
        if ((q >> PCB) & 1) {
            float2 f = upk(v[q]);
            float px = __shfl_xor_sync(0xffffffffu, f.x, mk);
            float py = __shfl_xor_sync(0xffffffffu, f.y, mk);
            v[q] = fma2(cc2, v[q], mul2(ssv2, pk2(py, px)));
        }
    }
}

template<int PTB>
__device__ __forceinline__ void crx_reg_tgt(u64* v, bool act, float cc, float ss)
{
    float ccl = act ? cc : 1.f, ssl = act ? ss : 0.f;
    u64 cc2 = pk2(ccl, ccl), ssv2 = pk2(ssl, -ssl);
    #pragma unroll
    for (int m = 0; m < 4; ++m) {
        int i0 = ((m >> PTB) << (PTB+1)) | (m & ((1 << PTB) - 1));
        int i1 = i0 | (1 << PTB);
        u64 a0 = v[i0], a1 = v[i1];
        v[i0] = fma2(cc2, a0, mul2(ssv2, swap2(a1)));
        v[i1] = fma2(cc2, a1, mul2(ssv2, swap2(a0)));
    }
}

// ----- cross-warp exchange gates (double-buffered smem, 1 bar each) ---------
struct Xch {
    u64* base; int tog; int tid;
    __device__ __forceinline__ u64* next() { u64* p = base + ((tog & 1) << 10); ++tog; return p; }
};

__device__ __forceinline__ void ry_warp(u64* v, Xch& X, int wb, float cc, float ss)
{
    u64* b = X.next();
    int tid = X.tid, xv = 32 << wb;
    #pragma unroll
    for (int i = 0; i < 8; ++i) b[i*128 + tid] = v[i];
    __syncthreads();
    float sg = ((tid >> (5 + wb)) & 1) ? ss : -ss;
    u64 cc2 = pk2(cc, cc), sg2 = pk2(sg, sg);
    #pragma unroll
    for (int i = 0; i < 8; ++i)
        v[i] = fma2(cc2, v[i], mul2(sg2, b[i*128 + (tid ^ xv)]));
}

__device__ __forceinline__ void crx_warp_tgt(u64* v, Xch& X, int twb, bool act, float cc, float ss)
{
    u64* b = X.next();
    int tid = X.tid, xv = 32 << twb;
    #pragma unroll
    for (int i = 0; i < 8; ++i) b[i*128 + tid] = v[i];
    __syncthreads();
    float ccl = act ? cc : 1.f, ssl = act ? ss : 0.f;
    u64 cc2 = pk2(ccl, ccl), ssv2 = pk2(ssl, -ssl);
    #pragma unroll
    for (int i = 0; i < 8; ++i)
        v[i] = fma2(cc2, v[i], mul2(ssv2, swap2(b[i*128 + (tid ^ xv)])));
}

__device__ __forceinline__ void crx_rw(u64* v, Xch& X, int twb, float cc, float ss)
{
    u64* b = X.next();
    int tid = X.tid, xv = 32 << twb;
    #pragma unroll
    for (int i = 0; i < 4; ++i) b[i*128 + tid] = v[4 + i];
    __syncthreads();
    u64 cc2 = pk2(cc, cc), ssv2 = pk2(ss, -ss);
    #pragma unroll
    for (int i = 0; i < 4; ++i)
        v[4 + i] = fma2(cc2, v[4 + i], mul2(ssv2, swap2(b[i*128 + (tid ^ xv)])));
}

// -------------------------------------------------------- layer pieces ------
#define SS(A) (sgn*(A).y)

__device__ __forceinline__ void ry_all(u64* v, Xch& X, const float2* __restrict__ ang,
                                       float sgn, int lane)
{
    ry_warp(v, X, 1, ang[0].x, SS(ang[0]));      // q0 -> bit9 (wb1)
    ry_warp(v, X, 0, ang[1].x, SS(ang[1]));      // q1 -> bit8 (wb0)
    ry_reg<2>(v, ang[2].x, SS(ang[2]));          // q2 -> bit7
    ry_reg<1>(v, ang[3].x, SS(ang[3]));
    ry_reg<0>(v, ang[4].x, SS(ang[4]));
    #pragma unroll 1
    for (int pl = 4; pl >= 0; --pl) {
        float2 cs = ang[9 - pl];
        ry_lane(v, pl, cs.x, sgn*cs.y, lane);
    }
}

// ring A: gate k = (ctrl bit k, tgt bit k-1 mod 10), angle ang[k]
__device__ __forceinline__ void ring_a(u64* v, Xch& X, const float2* __restrict__ ang,
                                       float sgn, int lane, int tid, bool rev)
{
    if (!rev) {
        crx_warp_tgt(v, X, 1, lane & 1, ang[0].x, SS(ang[0]));
        crx_shfl(v, 0, (lane >> 1) & 1, ang[1].x, SS(ang[1]));
        crx_shfl(v, 1, (lane >> 2) & 1, ang[2].x, SS(ang[2]));
        crx_shfl(v, 2, (lane >> 3) & 1, ang[3].x, SS(ang[3]));
        crx_shfl(v, 3, (lane >> 4) & 1, ang[4].x, SS(ang[4]));
        crx_rl<0>(v, 4, ang[5].x, SS(ang[5]));
        crx_rr<1,0>(v, ang[6].x, SS(ang[6]));
        crx_rr<2,1>(v, ang[7].x, SS(ang[7]));
        crx_reg_tgt<2>(v, (tid >> 5) & 1, ang[8].x, SS(ang[8]));
        crx_warp_tgt(v, X, 0, (tid >> 6) & 1, ang[9].x, SS(ang[9]));
    } else {
        crx_warp_tgt(v, X, 0, (tid >> 6) & 1, ang[9].x, SS(ang[9]));
        crx_reg_tgt<2>(v, (tid >> 5) & 1, ang[8].x, SS(ang[8]));
        crx_rr<2,1>(v, ang[7].x, SS(ang[7]));
        crx_rr<1,0>(v, ang[6].x, SS(ang[6]));
        crx_rl<0>(v, 4, ang[5].x, SS(ang[5]));
        crx_shfl(v, 3, (lane >> 4) & 1, ang[4].x, SS(ang[4]));
        crx_shfl(v, 2, (lane >> 3) & 1, ang[3].x, SS(ang[3]));
        crx_shfl(v, 1, (lane >> 2) & 1, ang[2].x, SS(ang[2]));
        crx_shfl(v, 0, (lane >> 1) & 1, ang[1].x, SS(ang[1]));
        crx_warp_tgt(v, X, 1, lane & 1, ang[0].x, SS(ang[0]));
    }
}

// ring B: k0(c0,t1) k1(c9,t0) k2(c8,t9) k3(c7,t8) k4(c6,t7)
//         k5(c5,t6) k6(c4,t5) k7(c3,t4) k8(c2,t3) k9(c1,t2)
__device__ __forceinline__ void ring_b(u64* v, Xch& X, const float2* __restrict__ ang,
                                       float sgn, int lane, int tid, bool rev)
{
    if (!rev) {
        crx_shfl(v, 1, lane & 1, ang[0].x, SS(ang[0]));
        crx_shfl(v, 0, (tid >> 6) & 1, ang[1].x, SS(ang[1]));
        crx_warp_tgt(v, X, 1, (tid >> 5) & 1, ang[2].x, SS(ang[2]));
        crx_rw(v, X, 0, ang[3].x, SS(ang[3]));
        crx_rr<1,2>(v, ang[4].x, SS(ang[4]));
        crx_rr<0,1>(v, ang[5].x, SS(ang[5]));
        crx_reg_tgt<0>(v, (lane >> 4) & 1, ang[6].x, SS(ang[6]));
        crx_shfl(v, 4, (lane >> 3) & 1, ang[7].x, SS(ang[7]));
        crx_shfl(v, 3, (lane >> 2) & 1, ang[8].x, SS(ang[8]));
        crx_shfl(v, 2, (lane >> 1) & 1, ang[9].x, SS(ang[9]));
    } else {
        crx_shfl(v, 2, (lane >> 1) & 1, ang[9].x, SS(ang[9]));
        crx_shfl(v, 3, (lane >> 2) & 1, ang[8].x, SS(ang[8]));
        crx_shfl(v, 4, (lane >> 3) & 1, ang[7].x, SS(ang[7]));
        crx_reg_tgt<0>(v, (lane >> 4) & 1, ang[6].x, SS(ang[6]));
        crx_rr<0,1>(v, ang[5].x, SS(ang[5]));
        crx_rr<1,2>(v, ang[4].x, SS(ang[4]));
        crx_rw(v, X, 0, ang[3].x, SS(ang[3]));
        crx_warp_tgt(v, X, 1, (tid >> 5) & 1, ang[2].x, SS(ang[2]));
        crx_shfl(v, 0, (tid >> 6) & 1, ang[1].x, SS(ang[1]));
        crx_shfl(v, 1, lane & 1, ang[0].x, SS(ang[0]));
    }
}

// ---------------------------------------------------------- select phase ----
__device__ void sel_phase(int c, int tid, int lane, u64* xbuf, float2* sang,
                          int nlayers, int useQff, int adjoint, int init)
{
    if (useQff) { if (tid < QROTS) sang[tid] = g_qff[tid]; }
    else { int ntot = nlayers * 40; if (tid < ntot) sang[tid] = g_csn[c*NROTS + tid]; }
    __syncthreads();

    Xch X{xbuf, 0, tid};
    u64 v[8];
    u64* gb = G_STATEU + ((size_t)c << 10);
    int base = (tid >> 5) * 256 + lane;
    if (init) {
        #pragma unroll
        for (int q = 0; q < 8; ++q) v[q] = 0ull;
        if (tid == 0) { float2 f = g_v0[c & 15]; v[0] = pk2(f.x, f.y); }
    } else {
        #pragma unroll
        for (int q = 0; q < 8; ++q) v[q] = gb[base + q*32];
    }

    if (!adjoint) {
        const float sgn = 1.f;
        #pragma unroll 1
        for (int l = 0; l < nlayers; ++l) {
            const float2* a = sang + 40*l;
            ry_all(v, X, a, sgn, lane);
            ring_a(v, X, a + 10, sgn, lane, tid, false);
            ry_all(v, X, a + 20, sgn, lane);
            ring_b(v, X, a + 30, sgn, lane, tid, false);
        }
    } else {
        const float sgn = -1.f;
        #pragma unroll 1
        for (int l = nlayers - 1; l >= 0; --l) {
            const float2* a = sang + 40*l;
            ring_b(v, X, a + 30, sgn, lane, tid, true);
            ry_all(v, X, a + 20, sgn, lane);
            ring_a(v, X, a + 10, sgn, lane, tid, true);
            ry_all(v, X, a, sgn, lane);
        }
    }

    #pragma unroll
    for (int q = 0; q < 8; ++q) gb[base + q*32] = v[q];
}

// ------------------------------------------------------------- anc phase ----
// CTA c = (b = c>>4, s-chunk = c&15, 64 s values). Tile 16a x 64s in smem.
__device__ void anc_phase(int c, int tid, int mi, u64* pool)
{
    u64* tile = pool;           // 1024 u64
    u64* sM   = pool + 1024;    // 256 u64
    int b = c >> 4, sc = c & 15;
    sM[tid]       = ((const u64*)g_M[mi])[tid];
    sM[128 + tid] = ((const u64*)g_M[mi])[128 + tid];
    size_t sb = ((size_t)b << 14) + ((size_t)sc << 6);
    #pragma unroll
    for (int i = 0; i < 8; ++i) {
        int idx = i*128 + tid;
        int a = idx >> 6, sj = idx & 63;
        tile[idx] = G_STATEU[sb + ((size_t)a << 10) + sj];
    }
    __syncthreads();
    #pragma unroll
    for (int i = 0; i < 8; ++i) {
        int idx = i*128 + tid;
        int a = idx >> 6, sj = idx & 63;
        u64 acc = 0ull;
        #pragma unroll
        for (int k = 0; k < 16; ++k) {
            float2 m = upk(sM[a*16 + k]);
            u64 xv = tile[k*64 + sj];
            acc = fma2(pk2(m.x, m.x), xv, acc);
            acc = fma2(pk2(-m.y, m.y), swap2(xv), acc);
        }
        G_STATEU[sb + ((size_t)a << 10) + sj] = acc;
    }
}

// ------------------------------------------------------------- exp phase ----
// CTA within-batch index qi = c&15 handles qubit qi (<10); others idle.
__device__ void exp_phase(int c, int tid, float* sred)
{
    int b = c >> 4, qi = c & 15;
    if (qi >= 10) return;
    int p = 9 - qi;
    const float2* st = G_STATE + ((size_t)b << 14);
    float cr = 0.f, ci = 0.f, zz = 0.f;
    #pragma unroll 4
    for (int pk_ = tid; pk_ < 8192; pk_ += 128) {
        int a = pk_ >> 9, m = pk_ & 511;
        int s0 = ((m >> p) << (p+1)) | (m & ((1 << p) - 1));
        int f0 = (a << 10) | s0;
        float2 a0 = st[f0];
        float2 a1 = st[f0 | (1 << p)];
        cr += a0.x*a1.x + a0.y*a1.y;
        ci += a0.x*a1.y - a0.y*a1.x;
        zz += (a0.x*a0.x + a0.y*a0.y) - (a1.x*a1.x + a1.y*a1.y);
    }
    #pragma unroll
    for (int off = 16; off; off >>= 1) {
        cr += __shfl_down_sync(0xffffffffu, cr, off);
        ci += __shfl_down_sync(0xffffffffu, ci, off);
        zz += __shfl_down_sync(0xffffffffu, zz, off);
    }
    int w = tid >> 5;
    if ((tid & 31) == 0) { sred[w*3+0] = cr; sred[w*3+1] = ci; sred[w*3+2] = zz; }
    __syncthreads();
    if (tid == 0) {
        float A = 0.f, Bv = 0.f, C = 0.f;
        #pragma unroll
        for (int ww = 0; ww < 4; ++ww) { A += sred[ww*3]; Bv += sred[ww*3+1]; C += sred[ww*3+2]; }
        g_ex[b*30 + qi]      = 2.f * A;
        g_ex[b*30 + 10 + qi] = 2.f * Bv;
        g_ex[b*30 + 20 + qi] = C;
    }
}

// -------------------------------------------------------------- mega --------
__global__ void __launch_bounds__(128, 2) mega(
    const float* __restrict__ x,
    const float* __restrict__ Wfp,
    const float* __restrict__ bfp,
    const float* __restrict__ prep_p,
    const float* __restrict__ sig_ang,
    const float* __restrict__ qff_p,
    const float* __restrict__ W_out,
    const float* __restrict__ b_out,
    float* __restrict__ out)
{
    int c = blockIdx.x;
    int bb = c >> 4;            // batch
    int cb = c & 15;            // index within batch
    int tid = threadIdx.x;
    int lane = tid & 31;
    __shared__ u64 xbuf[2048];
    __shared__ float2 sang[80];
    __shared__ float sred[12];
    __shared__ unsigned s_base;
    if (tid == 0) s_base = *(volatile unsigned*)&g_bsns[bb];
    __syncthreads();
    unsigned gen = s_base;

    // ----- P0: angles for (b,t) = c; each batch's leader also does setup -----
    {
        float* h = (float*)xbuf;
        int t = cb;
        if (tid < 64) {
            int f = tid;
            int k = f >> 1;
            float div = expf((float)(2*k) * (-logf(10000.0f) / 64.0f));
            float arg = (float)t * div;
            float pe = (f & 1) ? cosf(arg) : sinf(arg);
            h[f] = x[(bb*64 + f)*16 + t] + pe;
        }
        __syncthreads();
        if (tid < NROTS) {
            float acc = bfp[tid];
            const float* w = Wfp + tid*64;
            #pragma unroll
            for (int f = 0; f < 64; ++f) acc += h[f]*w[f];
            float sg = 1.0f / (1.0f + expf(-acc));
            float sn, cs;
            sincosf(3.14159265358979323846f * sg, &sn, &cs);
            g_csn[c*NROTS + tid] = make_float2(cs, sn);
        }
        if (cb == 0) {
            // batch leader: redundant global setup (identical values per batch)
            float2 (*sU)[16] = (float2(*)[16])(xbuf + 64);
            if (tid < 16) {
                float2 v[16];
                #pragma unroll
                for (int i = 0; i < 16; ++i) v[i] = make_float2(0.f, 0.f);
                v[tid] = make_float2(1.f, 0.f);
                for (int ly = 0; ly < 4; ++ly) {
                    for (int qi = 0; qi < 4; ++qi) {
                        int p = 3 - qi;
                        float thy = prep_p[(ly*4 + qi)*2 + 0];
                        float thz = prep_p[(ly*4 + qi)*2 + 1];
                        float cth, sth;
                        sincosf(0.5f*thy, &sth, &cth);
                        for (int m = 0; m < 8; ++m) {
                            int i0 = ((m >> p) << (p+1)) | (m & ((1 << p) - 1));
                            int i1 = i0 | (1 << p);
                            float2 a0 = v[i0], a1 = v[i1];
                            v[i0] = make_float2(cth*a0.x - sth*a1.x, cth*a0.y - sth*a1.y);
                            v[i1] = make_float2(sth*a0.x + cth*a1.x, sth*a0.y + cth*a1.y);
                        }
                        float cz, sz;
                        sincosf(0.5f*thz, &sz, &cz);
                        for (int i = 0; i < 16; ++i) {
                            float im = ((i >> p) & 1) ? sz : -sz;
                            float2 a = v[i];
                            v[i] = make_float2(cz*a.x - im*a.y, cz*a.y + im*a.x);
                        }
                    }
                    for (int i = 0; i < 3; ++i) {
                        int pc = 3 - i, pt = 2 - i;
                        for (int idx = 0; idx < 16; ++idx) {
                            if (((idx >> pc) & 1) == 1 && ((idx >> pt) & 1) == 0) {
                                int j = idx | (1 << pt);
                                float2 tmp = v[idx]; v[idx] = v[j]; v[j] = tmp;
                            }
                        }
                    }
                }
                #pragma unroll
                for (int r = 0; r < 16; ++r) sU[r][tid] = v[r];
            }
            __syncthreads();
            if (tid < 16) {
                float c0, s0;
                sincosf(sig_ang[0], &s0, &c0);
                float2 u = sU[tid][0];
                g_v0[tid] = make_float2(c0*u.x - s0*u.y, c0*u.y + s0*u.x);
            }
            if (tid >= 64 && tid < 64 + QROTS) {
                float cq, sq;
                sincosf(0.5f * qff_p[tid - 64], &sq, &cq);
                g_qff[tid - 64] = make_float2(cq, sq);
            }
            #pragma unroll 1
            for (int half = 0; half < 2; ++half) {
                int idx = half*128 + tid;
                int j = idx >> 4, k = idx & 15;
                for (int m = 0; m < 2; ++m) {
                    float cp, sp;
                    sincosf(sig_ang[m+1], &sp, &cp);
                    float2 acc = make_float2(0.f, 0.f);
                    #pragma unroll
                    for (int a = 0; a < 16; ++a) {
                        float2 uja = sU[j][a];
                        float2 uka = sU[k][a];
                        float dr = cp, di = (a == 0) ? sp : -sp;
                        float2 dc = make_float2(dr*uka.x + di*uka.y, di*uka.x - dr*uka.y);
                        acc.x += uja.x*dc.x - uja.y*dc.y;
                        acc.y += uja.x*dc.y + uja.y*dc.x;
                    }
                    g_M[m][j*16 + k] = acc;
                }
                float cp, sp;
                sincosf(sig_ang[3], &sp, &cp);
                float dr = cp, di = (j == 0) ? sp : -sp;
                float2 u2 = sU[k][j];
                g_M[2][j*16 + k] = make_float2(dr*u2.x + di*u2.y, di*u2.x - dr*u2.y);
            }
        }
    }
    bbar(bb, gen + 1);

    sel_phase(c, tid, lane, xbuf, sang, 2, 0, 0, 1);   // k=0 forward (init)
    bbar(bb, gen + 2);
    anc_phase(c, tid, 0, xbuf);
    bbar(bb, gen + 3);
    sel_phase(c, tid, lane, xbuf, sang, 2, 0, 1, 0);   // k=1 adjoint
    bbar(bb, gen + 4);
    anc_phase(c, tid, 1, xbuf);
    bbar(bb, gen + 5);
    sel_phase(c, tid, lane, xbuf, sang, 2, 0, 0, 0);   // k=2 forward
    bbar(bb, gen + 6);
    anc_phase(c, tid, 2, xbuf);
    bbar(bb, gen + 7);
    sel_phase(c, tid, lane, xbuf, sang, 1, 1, 0, 0);   // qff layer
    bbar(bb, gen + 8);
    exp_phase(c, tid, sred);
    bbar(bb, gen + 9);
    if (cb == 0 && tid < ODIM) {
        float acc = b_out[tid];
        #pragma unroll
        for (int j = 0; j < 30; ++j) acc += W_out[tid*30 + j] * g_ex[bb*30 + j];
        out[bb*ODIM + tid] = acc;
    }
}

// ------------------------------------------------------------ launch --------
extern "C" void kernel_launch(void* const* d_in, const int* in_sizes, int n_in,
                              void* d_out, int out_size)
{
    const float* x       = (const float*)d_in[0];
    const float* W_fp    = (const float*)d_in[1];
    const float* b_fp    = (const float*)d_in[2];
    const float* prep_p  = (const float*)d_in[3];
    const float* sig_ang = (const float*)d_in[4];
    const float* qff_p   = (const float*)d_in[5];
    const float* W_out   = (const float*)d_in[6];
    const float* b_out   = (const float*)d_in[7];
    float* out = (float*)d_out;

    mega<<<NCTA, 128>>>(x, W_fp, b_fp, prep_p, sig_ang, qff_p, W_out, b_out, out);
}

// round 14
// speedup vs baseline: 1.1979x; 1.0910x over previous
#include <cuda_runtime.h>
#include <math.h>

#define Bsz 16
#define Tn 16
#define FDIM 64
#define ODIM 8
#define NQ 10
#define NA 4
#define NROTS 80
#define QROTS 40
#define NS 1024
#define NANC 16
#define STATE_PER_B (NS*NANC)
#define TOTAL_AMPS (Bsz*STATE_PER_B)
#define NCTA 256

typedef unsigned long long u64;

__device__ float4 g_state4[TOTAL_AMPS/2];
#define G_STATE  ((float2*)g_state4)
#define G_STATEU ((u64*)g_state4)
__device__ float2 g_M[3][256];
__device__ float  g_expart[NCTA*30];
__device__ unsigned g_bcnt[16];
__device__ unsigned g_bsns[16];

// ------------------------------------------------------- packed f32x2 ops ---
__device__ __forceinline__ u64 pk2(float x, float y) {
    u64 r; asm("mov.b64 %0, {%1, %2};" : "=l"(r) : "f"(x), "f"(y)); return r;
}
__device__ __forceinline__ float2 upk(u64 a) {
    float2 f; asm("mov.b64 {%0, %1}, %2;" : "=f"(f.x), "=f"(f.y) : "l"(a)); return f;
}
__device__ __forceinline__ u64 mul2(u64 a, u64 b) {
    u64 d; asm("mul.rn.f32x2 %0, %1, %2;" : "=l"(d) : "l"(a), "l"(b)); return d;
}
__device__ __forceinline__ u64 fma2(u64 a, u64 b, u64 c) {
    u64 d; asm("fma.rn.f32x2 %0, %1, %2, %3;" : "=l"(d) : "l"(a), "l"(b), "l"(c)); return d;
}
__device__ __forceinline__ u64 swap2(u64 a) {
    float2 f = upk(a); return pk2(f.y, f.x);
}

// ----------------------------------------------------- per-batch barrier ----
__device__ __forceinline__ void bbar(int b, unsigned target)
{
    __syncthreads();
    if (threadIdx.x == 0) {
        __threadfence();
        unsigned arrived = atomicAdd(&g_bcnt[b], 1u) + 1u;
        if (arrived == 16u) {
            g_bcnt[b] = 0u;
            __threadfence();
            atomicExch(&g_bsns[b], target);
        } else {
            while ((int)(*(volatile unsigned*)&g_bsns[b] - target) < 0) { }
        }
        __threadfence();
    }
    __syncthreads();
}

// ------------------------------------------------------- gate primitives ----
// layout: amplitude s: lane = s[4:0], reg = s[7:5] (8 u64/lane), warp = s[9:8].

template<int PB>
__device__ __forceinline__ void ry_reg(u64* v, float cc, float ss)
{
    u64 cc2 = pk2(cc, cc), ss2 = pk2(ss, ss), nss2 = pk2(-ss, -ss);
    #pragma unroll
    for (int m = 0; m < 4; ++m) {
        int i0 = ((m >> PB) << (PB+1)) | (m & ((1 << PB) - 1));
        int i1 = i0 | (1 << PB);
        u64 a0 = v[i0], a1 = v[i1];
        v[i0] = fma2(cc2, a0, mul2(nss2, a1));
        v[i1] = fma2(cc2, a1, mul2(ss2, a0));
    }
}

__device__ __forceinline__ void ry_lane(u64* v, int pl, float cc, float ss, int lane)
{
    float sg = ((lane >> pl) & 1) ? ss : -ss;
    u64 cc2 = pk2(cc, cc), sg2 = pk2(sg, sg);
    int mk = 1 << pl;
    #pragma unroll
    for (int q = 0; q < 8; ++q) {
        float2 f = upk(v[q]);
        float px = __shfl_xor_sync(0xffffffffu, f.x, mk);
        float py = __shfl_xor_sync(0xffffffffu, f.y, mk);
        v[q] = fma2(cc2, v[q], mul2(sg2, pk2(px, py)));
    }
}

template<int PCB, int PTB>
__device__ __forceinline__ void crx_rr(u64* v, float cc, float ss)
{
    u64 cc2 = pk2(cc, cc), ssv2 = pk2(ss, -ss);
    #pragma unroll
    for (int i = 0; i < 8; ++i) {
        if ((((i >> PCB) & 1) == 1) && (((i >> PTB) & 1) == 0)) {
            int i1 = i | (1 << PTB);
            u64 a0 = v[i], a1 = v[i1];
            v[i]  = fma2(cc2, a0, mul2(ssv2, swap2(a1)));
            v[i1] = fma2(cc2, a1, mul2(ssv2, swap2(a0)));
        }
    }
}

__device__ __forceinline__ void crx_shfl(u64* v, int pt, bool act, float cc, float ss)
{
    float ccl = act ? cc : 1.f, ssl = act ? ss : 0.f;
    u64 cc2 = pk2(ccl, ccl), ssv2 = pk2(ssl, -ssl);
    int mk = 1 << pt;
    #pragma unroll
    for (int q = 0; q < 8; ++q) {
        float2 f = upk(v[q]);
        float px = __shfl_xor_sync(0xffffffffu, f.x, mk);
        float py = __shfl_xor_sync(0xffffffffu, f.y, mk);
        v[q] = fma2(cc2, v[q], mul2(ssv2, pk2(py, px)));
    }
}

template<int PCB>
__device__ __forceinline__ void crx_rl(u64* v, int pt, float cc, float ss)
{
    u64 cc2 = pk2(cc, cc), ssv2 = pk2(ss, -ss);
    int mk = 1 << pt;
    #pragma unroll
    for (int q = 0; q < 8; ++q) {
        if ((q >> PCB) & 1) {
            float2 f = upk(v[q]);
            float px = __shfl_xor_sync(0xffffffffu, f.x, mk);
            float py = __shfl_xor_sync(0xffffffffu, f.y, mk);
            v[q] = fma2(cc2, v[q], mul2(ssv2, pk2(py, px)));
        }
    }
}

template<int PTB>
__device__ __forceinline__ void crx_reg_tgt(u64* v, bool act, float cc, float ss)
{
    float ccl = act ? cc : 1.f, ssl = act ? ss : 0.f;
    u64 cc2 = pk2(ccl, ccl), ssv2 = pk2(ssl, -ssl);
    #pragma unroll
    for (int m = 0; m < 4; ++m) {
        int i0 = ((m >> PTB) << (PTB+1)) | (m & ((1 << PTB) - 1));
        int i1 = i0 | (1 << PTB);
        u64 a0 = v[i0], a1 = v[i1];
        v[i0] = fma2(cc2, a0, mul2(ssv2, swap2(a1)));
        v[i1] = fma2(cc2, a1, mul2(ssv2, swap2(a0)));
    }
}

// ----- cross-warp exchange gates (double-buffered smem, 1 bar each) ---------
struct Xch {
    u64* base; int tog; int tid;
    __device__ __forceinline__ u64* next() { u64* p = base + ((tog & 1) << 10); ++tog; return p; }
};

__device__ __forceinline__ void ry_warp(u64* v, Xch& X, int wb, float cc, float ss)
{
    u64* b = X.next();
    int tid = X.tid, xv = 32 << wb;
    #pragma unroll
    for (int i = 0; i < 8; ++i) b[i*128 + tid] = v[i];
    __syncthreads();
    float sg = ((tid >> (5 + wb)) & 1) ? ss : -ss;
    u64 cc2 = pk2(cc, cc), sg2 = pk2(sg, sg);
    #pragma unroll
    for (int i = 0; i < 8; ++i)
        v[i] = fma2(cc2, v[i], mul2(sg2, b[i*128 + (tid ^ xv)]));
}

__device__ __forceinline__ void crx_warp_tgt(u64* v, Xch& X, int twb, bool act, float cc, float ss)
{
    u64* b = X.next();
    int tid = X.tid, xv = 32 << twb;
    #pragma unroll
    for (int i = 0; i < 8; ++i) b[i*128 + tid] = v[i];
    __syncthreads();
    float ccl = act ? cc : 1.f, ssl = act ? ss : 0.f;
    u64 cc2 = pk2(ccl, ccl), ssv2 = pk2(ssl, -ssl);
    #pragma unroll
    for (int i = 0; i < 8; ++i)
        v[i] = fma2(cc2, v[i], mul2(ssv2, swap2(b[i*128 + (tid ^ xv)])));
}

__device__ __forceinline__ void crx_rw(u64* v, Xch& X, int twb, float cc, float ss)
{
    u64* b = X.next();
    int tid = X.tid, xv = 32 << twb;
    #pragma unroll
    for (int i = 0; i < 4; ++i) b[i*128 + tid] = v[4 + i];
    __syncthreads();
    u64 cc2 = pk2(cc, cc), ssv2 = pk2(ss, -ss);
    #pragma unroll
    for (int i = 0; i < 4; ++i)
        v[4 + i] = fma2(cc2, v[4 + i], mul2(ssv2, swap2(b[i*128 + (tid ^ xv)])));
}

// -------------------------------------------------------- layer pieces ------
#define SS(A) (sgn*(A).y)

__device__ __forceinline__ void ry_all(u64* v, Xch& X, const float2* __restrict__ ang,
                                       float sgn, int lane)
{
    ry_warp(v, X, 1, ang[0].x, SS(ang[0]));
    ry_warp(v, X, 0, ang[1].x, SS(ang[1]));
    ry_reg<2>(v, ang[2].x, SS(ang[2]));
    ry_reg<1>(v, ang[3].x, SS(ang[3]));
    ry_reg<0>(v, ang[4].x, SS(ang[4]));
    #pragma unroll 1
    for (int pl = 4; pl >= 0; --pl) {
        float2 cs = ang[9 - pl];
        ry_lane(v, pl, cs.x, sgn*cs.y, lane);
    }
}

__device__ __forceinline__ void ring_a(u64* v, Xch& X, const float2* __restrict__ ang,
                                       float sgn, int lane, int tid, bool rev)
{
    if (!rev) {
        crx_warp_tgt(v, X, 1, lane & 1, ang[0].x, SS(ang[0]));
        crx_shfl(v, 0, (lane >> 1) & 1, ang[1].x, SS(ang[1]));
        crx_shfl(v, 1, (lane >> 2) & 1, ang[2].x, SS(ang[2]));
        crx_shfl(v, 2, (lane >> 3) & 1, ang[3].x, SS(ang[3]));
        crx_shfl(v, 3, (lane >> 4) & 1, ang[4].x, SS(ang[4]));
        crx_rl<0>(v, 4, ang[5].x, SS(ang[5]));
        crx_rr<1,0>(v, ang[6].x, SS(ang[6]));
        crx_rr<2,1>(v, ang[7].x, SS(ang[7]));
        crx_reg_tgt<2>(v, (tid >> 5) & 1, ang[8].x, SS(ang[8]));
        crx_warp_tgt(v, X, 0, (tid >> 6) & 1, ang[9].x, SS(ang[9]));
    } else {
        crx_warp_tgt(v, X, 0, (tid >> 6) & 1, ang[9].x, SS(ang[9]));
        crx_reg_tgt<2>(v, (tid >> 5) & 1, ang[8].x, SS(ang[8]));
        crx_rr<2,1>(v, ang[7].x, SS(ang[7]));
        crx_rr<1,0>(v, ang[6].x, SS(ang[6]));
        crx_rl<0>(v, 4, ang[5].x, SS(ang[5]));
        crx_shfl(v, 3, (lane >> 4) & 1, ang[4].x, SS(ang[4]));
        crx_shfl(v, 2, (lane >> 3) & 1, ang[3].x, SS(ang[3]));
        crx_shfl(v, 1, (lane >> 2) & 1, ang[2].x, SS(ang[2]));
        crx_shfl(v, 0, (lane >> 1) & 1, ang[1].x, SS(ang[1]));
        crx_warp_tgt(v, X, 1, lane & 1, ang[0].x, SS(ang[0]));
    }
}

__device__ __forceinline__ void ring_b(u64* v, Xch& X, const float2* __restrict__ ang,
                                       float sgn, int lane, int tid, bool rev)
{
    if (!rev) {
        crx_shfl(v, 1, lane & 1, ang[0].x, SS(ang[0]));
        crx_shfl(v, 0, (tid >> 6) & 1, ang[1].x, SS(ang[1]));
        crx_warp_tgt(v, X, 1, (tid >> 5) & 1, ang[2].x, SS(ang[2]));
        crx_rw(v, X, 0, ang[3].x, SS(ang[3]));
        crx_rr<1,2>(v, ang[4].x, SS(ang[4]));
        crx_rr<0,1>(v, ang[5].x, SS(ang[5]));
        crx_reg_tgt<0>(v, (lane >> 4) & 1, ang[6].x, SS(ang[6]));
        crx_shfl(v, 4, (lane >> 3) & 1, ang[7].x, SS(ang[7]));
        crx_shfl(v, 3, (lane >> 2) & 1, ang[8].x, SS(ang[8]));
        crx_shfl(v, 2, (lane >> 1) & 1, ang[9].x, SS(ang[9]));
    } else {
        crx_shfl(v, 2, (lane >> 1) & 1, ang[9].x, SS(ang[9]));
        crx_shfl(v, 3, (lane >> 2) & 1, ang[8].x, SS(ang[8]));
        crx_shfl(v, 4, (lane >> 3) & 1, ang[7].x, SS(ang[7]));
        crx_reg_tgt<0>(v, (lane >> 4) & 1, ang[6].x, SS(ang[6]));
        crx_rr<0,1>(v, ang[5].x, SS(ang[5]));
        crx_rr<1,2>(v, ang[4].x, SS(ang[4]));
        crx_rw(v, X, 0, ang[3].x, SS(ang[3]));
        crx_warp_tgt(v, X, 1, (tid >> 5) & 1, ang[2].x, SS(ang[2]));
        crx_shfl(v, 0, (tid >> 6) & 1, ang[1].x, SS(ang[1]));
        crx_shfl(v, 1, lane & 1, ang[0].x, SS(ang[0]));
    }
}

// --------------------------------------------------- in-register expvals ----
// Per-CTA partial sums over its own (b,a) block; matches ref 2*Re / 2*Im / Z.
__device__ void exp_partial(int c, int tid, int lane, u64* v, u64* xbuf)
{
    float X[10], Y[10], Z[10];
    #pragma unroll
    for (int i = 0; i < 10; ++i) { X[i] = 0.f; Y[i] = 0.f; Z[i] = 0.f; }

    // lane bits p=0..4 -> qubit i=9-p
    #pragma unroll
    for (int p = 0; p < 5; ++p) {
        int i = 9 - p;
        int mk = 1 << p;
        float sg = ((lane >> p) & 1) ? -1.f : 1.f;
        #pragma unroll
        for (int q = 0; q < 8; ++q) {
            float2 f = upk(v[q]);
            float px = __shfl_xor_sync(0xffffffffu, f.x, mk);
            float py = __shfl_xor_sync(0xffffffffu, f.y, mk);
            X[i] += f.x*px + f.y*py;
            Y[i] += sg*(f.x*py - f.y*px);
            Z[i] += sg*(f.x*f.x + f.y*f.y);
        }
    }
    // reg bits pb=0..2 -> qubit i=4-pb
    #pragma unroll
    for (int pb = 0; pb < 3; ++pb) {
        int i = 4 - pb;
        #pragma unroll
        for (int m = 0; m < 4; ++m) {
            int i0 = ((m >> pb) << (pb+1)) | (m & ((1 << pb) - 1));
            int i1 = i0 | (1 << pb);
            float2 a = upk(v[i0]), cc = upk(v[i1]);
            X[i] += 2.f*(a.x*cc.x + a.y*cc.y);
            Y[i] += 2.f*(a.x*cc.y - a.y*cc.x);
            Z[i] += (a.x*a.x + a.y*a.y) - (cc.x*cc.x + cc.y*cc.y);
        }
    }
    // warp bits wb=0,1 -> qubit i=1-wb (one smem exchange serves both)
    #pragma unroll
    for (int q = 0; q < 8; ++q) xbuf[q*128 + tid] = v[q];
    __syncthreads();
    #pragma unroll
    for (int wb = 0; wb < 2; ++wb) {
        int i = 1 - wb;
        int pr = tid ^ (32 << wb);
        float sg = ((tid >> (5 + wb)) & 1) ? -1.f : 1.f;
        #pragma unroll
        for (int q = 0; q < 8; ++q) {
            float2 g = upk(xbuf[q*128 + pr]);
            float2 f = upk(v[q]);
            X[i] += f.x*g.x + f.y*g.y;
            Y[i] += sg*(f.x*g.y - f.y*g.x);
            Z[i] += sg*(f.x*f.x + f.y*f.y);
        }
    }
    __syncthreads();
    // warp-level reduce, then CTA reduce in smem
    #pragma unroll
    for (int i = 0; i < 10; ++i) {
        #pragma unroll
        for (int off = 16; off; off >>= 1) {
            X[i] += __shfl_down_sync(0xffffffffu, X[i], off);
            Y[i] += __shfl_down_sync(0xffffffffu, Y[i], off);
            Z[i] += __shfl_down_sync(0xffffffffu, Z[i], off);
        }
    }
    float* red = (float*)xbuf;
    int w = tid >> 5;
    if (lane == 0) {
        #pragma unroll
        for (int i = 0; i < 10; ++i) {
            red[w*30 + i]      = X[i];
            red[w*30 + 10 + i] = Y[i];
            red[w*30 + 20 + i] = Z[i];
        }
    }
    __syncthreads();
    if (tid < 30)
        g_expart[c*30 + tid] = red[tid] + red[30 + tid] + red[60 + tid] + red[90 + tid];
}

// ---------------------------------------------------------- select phase ----
__device__ void sel_phase(int c, int tid, int lane, u64* xbuf,
                          const float2* __restrict__ sang, const float2* sv0,
                          int nlayers, int adjoint, int init, int store, int doExp)
{
    Xch X{xbuf, 0, tid};
    u64 v[8];
    u64* gb = G_STATEU + ((size_t)c << 10);
    int base = (tid >> 5) * 256 + lane;
    if (init) {
        #pragma unroll
        for (int q = 0; q < 8; ++q) v[q] = 0ull;
        if (tid == 0) { float2 f = sv0[c & 15]; v[0] = pk2(f.x, f.y); }
    } else {
        #pragma unroll
        for (int q = 0; q < 8; ++q) v[q] = gb[base + q*32];
    }

    if (!adjoint) {
        const float sgn = 1.f;
        #pragma unroll 1
        for (int l = 0; l < nlayers; ++l) {
            const float2* a = sang + 40*l;
            ry_all(v, X, a, sgn, lane);
            ring_a(v, X, a + 10, sgn, lane, tid, false);
            ry_all(v, X, a + 20, sgn, lane);
            ring_b(v, X, a + 30, sgn, lane, tid, false);
        }
    } else {
        const float sgn = -1.f;
        #pragma unroll 1
        for (int l = nlayers - 1; l >= 0; --l) {
            const float2* a = sang + 40*l;
            ring_b(v, X, a + 30, sgn, lane, tid, true);
            ry_all(v, X, a + 20, sgn, lane);
            ring_a(v, X, a + 10, sgn, lane, tid, true);
            ry_all(v, X, a, sgn, lane);
        }
    }

    if (store) {
        #pragma unroll
        for (int q = 0; q < 8; ++q) gb[base + q*32] = v[q];
    }
    if (doExp) exp_partial(c, tid, lane, v, xbuf);
}

// ------------------------------------------------------------- anc phase ----
__device__ void anc_phase(int c, int tid, int mi, u64* pool)
{
    u64* tile = pool;
    u64* sM   = pool + 1024;
    int b = c >> 4, sc = c & 15;
    sM[tid]       = ((const u64*)g_M[mi])[tid];
    sM[128 + tid] = ((const u64*)g_M[mi])[128 + tid];
    size_t sb = ((size_t)b << 14) + ((size_t)sc << 6);
    #pragma unroll
    for (int i = 0; i < 8; ++i) {
        int idx = i*128 + tid;
        int a = idx >> 6, sj = idx & 63;
        tile[idx] = G_STATEU[sb + ((size_t)a << 10) + sj];
    }
    __syncthreads();
    #pragma unroll
    for (int i = 0; i < 8; ++i) {
        int idx = i*128 + tid;
        int a = idx >> 6, sj = idx & 63;
        u64 acc = 0ull;
        #pragma unroll
        for (int k = 0; k < 16; ++k) {
            float2 m = upk(sM[a*16 + k]);
            u64 xv = tile[k*64 + sj];
            acc = fma2(pk2(m.x, m.x), xv, acc);
            acc = fma2(pk2(-m.y, m.y), swap2(xv), acc);
        }
        G_STATEU[sb + ((size_t)a << 10) + sj] = acc;
    }
}

// -------------------------------------------------------------- mega --------
__global__ void __launch_bounds__(128, 2) mega(
    const float* __restrict__ x,
    const float* __restrict__ Wfp,
    const float* __restrict__ bfp,
    const float* __restrict__ prep_p,
    const float* __restrict__ sig_ang,
    const float* __restrict__ qff_p,
    const float* __restrict__ W_out,
    const float* __restrict__ b_out,
    float* __restrict__ out)
{
    int c = blockIdx.x;
    int bb = c >> 4;
    int cb = c & 15;
    int tid = threadIdx.x;
    int lane = tid & 31;
    __shared__ u64 xbuf[2048];
    __shared__ float2 sang[80];
    __shared__ float2 sqff[40];
    __shared__ float2 sv0[16];
    __shared__ unsigned s_base;
    if (tid == 0) s_base = *(volatile unsigned*)&g_bsns[bb];
    __syncthreads();
    unsigned gen = s_base;

    // ----- P0: local angles, local v0, leader publishes g_M. No batch bar. --
    {
        float* h = (float*)xbuf;                 // bytes [0,256)
        if (tid < 64) {
            int f = tid;
            int k = f >> 1;
            float div = expf((float)(2*k) * (-logf(10000.0f) / 64.0f));
            float arg = (float)cb * div;
            float pe = (f & 1) ? cosf(arg) : sinf(arg);
            h[f] = x[(bb*64 + f)*16 + cb] + pe;
        }
        __syncthreads();
        if (tid < NROTS) {
            float acc = bfp[tid];
            const float* w = Wfp + tid*64;
            #pragma unroll
            for (int f = 0; f < 64; ++f) acc += h[f]*w[f];
            float sg = 1.0f / (1.0f + expf(-acc));
            float sn, cs;
            sincosf(3.14159265358979323846f * sg, &sn, &cs);
            sang[tid] = make_float2(cs, sn);
        }
        if (tid >= 88 && tid < 88 + QROTS) {
            float cq, sq;
            sincosf(0.5f * qff_p[tid - 88], &sq, &cq);
            sqff[tid - 88] = make_float2(cq, sq);
        }
        __syncthreads();                         // h dead
        float2 (*sU)[16] = (float2(*)[16])(xbuf + 64);   // bytes [512,2560)
        if (tid < 16) {
            float2 v[16];
            #pragma unroll
            for (int i = 0; i < 16; ++i) v[i] = make_float2(0.f, 0.f);
            v[tid] = make_float2(1.f, 0.f);
            for (int ly = 0; ly < 4; ++ly) {
                for (int qi = 0; qi < 4; ++qi) {
                    int p = 3 - qi;
                    float thy = prep_p[(ly*4 + qi)*2 + 0];
                    float thz = prep_p[(ly*4 + qi)*2 + 1];
                    float cth, sth;
                    sincosf(0.5f*thy, &sth, &cth);
                    for (int m = 0; m < 8; ++m) {
                        int i0 = ((m >> p) << (p+1)) | (m & ((1 << p) - 1));
                        int i1 = i0 | (1 << p);
                        float2 a0 = v[i0], a1 = v[i1];
                        v[i0] = make_float2(cth*a0.x - sth*a1.x, cth*a0.y - sth*a1.y);
                        v[i1] = make_float2(sth*a0.x + cth*a1.x, sth*a0.y + cth*a1.y);
                    }
                    float cz, sz;
                    sincosf(0.5f*thz, &sz, &cz);
                    for (int i = 0; i < 16; ++i) {
                        float im = ((i >> p) & 1) ? sz : -sz;
                        float2 a = v[i];
                        v[i] = make_float2(cz*a.x - im*a.y, cz*a.y + im*a.x);
                    }
                }
                for (int i = 0; i < 3; ++i) {
                    int pc = 3 - i, pt = 2 - i;
                    for (int idx = 0; idx < 16; ++idx) {
                        if (((idx >> pc) & 1) == 1 && ((idx >> pt) & 1) == 0) {
                            int j = idx | (1 << pt);
                            float2 tmp = v[idx]; v[idx] = v[j]; v[j] = tmp;
                        }
                    }
                }
            }
            #pragma unroll
            for (int r = 0; r < 16; ++r) sU[r][tid] = v[r];
        }
        __syncthreads();
        if (tid < 16) {
            float c0, s0;
            sincosf(sig_ang[0], &s0, &c0);
            float2 u = sU[tid][0];
            sv0[tid] = make_float2(c0*u.x - s0*u.y, c0*u.y + s0*u.x);
        }
        if (cb == 0) {      // batch leader publishes g_M (identical per batch)
            #pragma unroll 1
            for (int half = 0; half < 2; ++half) {
                int idx = half*128 + tid;
                int j = idx >> 4, k = idx & 15;
                for (int m = 0; m < 2; ++m) {
                    float cp, sp;
                    sincosf(sig_ang[m+1], &sp, &cp);
                    float2 acc = make_float2(0.f, 0.f);
                    #pragma unroll
                    for (int a = 0; a < 16; ++a) {
                        float2 uja = sU[j][a];
                        float2 uka = sU[k][a];
                        float dr = cp, di = (a == 0) ? sp : -sp;
                        float2 dc = make_float2(dr*uka.x + di*uka.y, di*uka.x - dr*uka.y);
                        acc.x += uja.x*dc.x - uja.y*dc.y;
                        acc.y += uja.x*dc.y + uja.y*dc.x;
                    }
                    g_M[m][j*16 + k] = acc;
                }
                float cp, sp;
                sincosf(sig_ang[3], &sp, &cp);
                float dr = cp, di = (j == 0) ? sp : -sp;
                float2 u2 = sU[k][j];
                g_M[2][j*16 + k] = make_float2(dr*u2.x + di*u2.y, di*u2.x - dr*u2.y);
            }
        }
        __syncthreads();
    }

    sel_phase(c, tid, lane, xbuf, sang, sv0, 2, 0, 1, 1, 0);   // k=0 fwd (init)
    bbar(bb, gen + 1);
    anc_phase(c, tid, 0, xbuf);
    bbar(bb, gen + 2);
    sel_phase(c, tid, lane, xbuf, sang, sv0, 2, 1, 0, 1, 0);   // k=1 adjoint
    bbar(bb, gen + 3);
    anc_phase(c, tid, 1, xbuf);
    bbar(bb, gen + 4);
    sel_phase(c, tid, lane, xbuf, sang, sv0, 2, 0, 0, 1, 0);   // k=2 fwd
    bbar(bb, gen + 5);
    anc_phase(c, tid, 2, xbuf);
    bbar(bb, gen + 6);
    sel_phase(c, tid, lane, xbuf, sqff, sv0, 1, 0, 0, 0, 1);   // qff + expvals
    bbar(bb, gen + 7);

    if (cb == 0) {
        float* exf = (float*)sang;      // sang dead
        if (tid < 30) {
            float s = 0.f;
            #pragma unroll
            for (int j = 0; j < 16; ++j) s += g_expart[(bb*16 + j)*30 + tid];
            exf[tid] = s;
        }
        __syncthreads();
        if (tid < ODIM) {
            float acc = b_out[tid];
            #pragma unroll
            for (int j = 0; j < 30; ++j) acc += W_out[tid*30 + j] * exf[j];
            out[bb*ODIM + tid] = acc;
        }
    }
}

// ------------------------------------------------------------ launch --------
extern "C" void kernel_launch(void* const* d_in, const int* in_sizes, int n_in,
                              void* d_out, int out_size)
{
    const float* x       = (const float*)d_in[0];
    const float* W_fp    = (const float*)d_in[1];
    const float* b_fp    = (const float*)d_in[2];
    const float* prep_p  = (const float*)d_in[3];
    const float* sig_ang = (const float*)d_in[4];
    const float* qff_p   = (const float*)d_in[5];
    const float* W_out   = (const float*)d_in[6];
    const float* b_out   = (const float*)d_in[7];
    float* out = (float*)d_out;

    mega<<<NCTA, 128>>>(x, W_fp, b_fp, prep_p, sig_ang, qff_p, W_out, b_out, out);
}